// round 10
// baseline (speedup 1.0000x reference)
#include <cuda_runtime.h>
#include <cuda_bf16.h>
#include <math.h>

#define BATCH 2
#define L 1024
#define BL 2048
#define DIM 1152
#define QKVD 3456          // 3*DIM
#define NHEADS 16
#define HDIM 72
#define HPAD 80
#define FF 4304
#define FF_PAD 4352
#define GUD 8608           // 2*FF
#define NLAYERS 4
#define PATCHD 768
#define EPS 1e-6f

typedef __nv_bfloat16 bf16;

// ---------------- f32 scratch ----------------
__device__ float g_x[BL * DIM];
__device__ float g_qkv[(size_t)BL * QKVD];
__device__ float g_o[BL * DIM];
__device__ float g_gateup[(size_t)BL * GUD];

// ---------------- bf16 hi/lo activation scratch ----------------
__device__ bf16 g_patH[BL * PATCHD], g_patL[BL * PATCHD];
__device__ bf16 g_hH[BL * DIM], g_hL[BL * DIM];
__device__ bf16 g_qpH[BL * NHEADS * HPAD], g_qpL[BL * NHEADS * HPAD];
__device__ bf16 g_kpH[BL * NHEADS * HPAD], g_kpL[BL * NHEADS * HPAD];
__device__ bf16 g_vtH[BATCH * NHEADS * HPAD * L], g_vtL[BATCH * NHEADS * HPAD * L];
__device__ bf16 g_attH[BL * DIM], g_attL[BL * DIM];
__device__ bf16 g_gH[(size_t)BL * FF_PAD], g_gL[(size_t)BL * FF_PAD];

// ---------------- pre-split transposed weights [N][K] ----------------
__device__ bf16 g_WpH[DIM * PATCHD], g_WpL[DIM * PATCHD];
__device__ bf16 g_WqkvH[(size_t)NLAYERS * QKVD * DIM], g_WqkvL[(size_t)NLAYERS * QKVD * DIM];
__device__ bf16 g_WoH[NLAYERS * DIM * DIM], g_WoL[NLAYERS * DIM * DIM];
__device__ bf16 g_WguH[(size_t)NLAYERS * GUD * DIM], g_WguL[(size_t)NLAYERS * GUD * DIM];
__device__ bf16 g_WdH[(size_t)NLAYERS * DIM * FF_PAD], g_WdL[(size_t)NLAYERS * DIM * FF_PAD];

__device__ __forceinline__ void splitStore(float v, bf16* H, bf16* Lo, size_t idx) {
    bf16 h = __float2bfloat16(v);
    H[idx] = h;
    Lo[idx] = __float2bfloat16(v - __bfloat162float(h));
}
__device__ __forceinline__ unsigned smem_u32(const void* p) {
    unsigned a;
    asm("{ .reg .u64 t; cvta.to.shared.u64 t, %1; cvt.u32.u64 %0, t; }" : "=r"(a) : "l"(p));
    return a;
}
__device__ __forceinline__ void mma_bf16(float c[4], const unsigned a[4], unsigned b0,
                                         unsigned b1) {
    asm volatile(
        "mma.sync.aligned.m16n8k16.row.col.f32.bf16.bf16.f32 "
        "{%0,%1,%2,%3}, {%4,%5,%6,%7}, {%8,%9}, {%0,%1,%2,%3};"
        : "+f"(c[0]), "+f"(c[1]), "+f"(c[2]), "+f"(c[3])
        : "r"(a[0]), "r"(a[1]), "r"(a[2]), "r"(a[3]), "r"(b0), "r"(b1));
}
__device__ __forceinline__ void mma3(float c[4], const unsigned ah[4], const unsigned al[4],
                                     unsigned bh0, unsigned bh1, unsigned bl0, unsigned bl1) {
    mma_bf16(c, ah, bh0, bh1);
    mma_bf16(c, ah, bl0, bl1);
    mma_bf16(c, al, bh0, bh1);
}
__device__ __forceinline__ void ldsm4(unsigned addr, unsigned& r0, unsigned& r1, unsigned& r2,
                                      unsigned& r3) {
    asm volatile("ldmatrix.sync.aligned.m8n8.x4.shared.b16 {%0,%1,%2,%3}, [%4];"
                 : "=r"(r0), "=r"(r1), "=r"(r2), "=r"(r3)
                 : "r"(addr));
}
__device__ __forceinline__ void pack2(float x, float y, unsigned& hi, unsigned& lo) {
    __nv_bfloat162 h = __floats2bfloat162_rn(x, y);
    __nv_bfloat162 l = __floats2bfloat162_rn(x - __low2float(h), y - __high2float(h));
    hi = *reinterpret_cast<unsigned*>(&h);
    lo = *reinterpret_cast<unsigned*>(&l);
}
__device__ __forceinline__ void cp16(unsigned dst, const void* src, unsigned nbytes) {
    asm volatile("cp.async.cg.shared.global [%0], [%1], 16, %2;"
                 :: "r"(dst), "l"(src), "r"(nbytes) : "memory");
}
#define CP_COMMIT() asm volatile("cp.async.commit_group;" ::: "memory")
#define CP_WAIT1()  asm volatile("cp.async.wait_group 1;" ::: "memory")

// =====================================================================================
// prepack: transpose W[K][N] -> hi/lo bf16 [N][ldo] (k-contiguous)
// =====================================================================================
__global__ void prepack_kernel(const float* __restrict__ W, bf16* __restrict__ H,
                               bf16* __restrict__ Lo, int K, int N, int ldo) {
    __shared__ float t[32][33];
    int tx = threadIdx.x, ty = threadIdx.y;
    int n0 = blockIdx.x * 32, k0 = blockIdx.y * 32;
#pragma unroll
    for (int j = 0; j < 4; j++) {
        int k = k0 + ty + j * 8, n = n0 + tx;
        if (k < K && n < N) t[ty + j * 8][tx] = W[(size_t)k * N + n];
    }
    __syncthreads();
#pragma unroll
    for (int j = 0; j < 4; j++) {
        int n = n0 + ty + j * 8, k = k0 + tx;
        if (k < K && n < N) splitStore(t[tx][ty + j * 8], H, Lo, (size_t)n * ldo + k);
    }
}

// =====================================================================================
// NT tensor-core GEMM (3xBF16, cp.async 3-stage pipeline, ldmatrix consumer)
//   C[M,N] = A[M,K] @ B[N,K]^T   (both k-contiguous), f32 out.
//   M%128==0, K%16==0; N tail guarded (zero-fill).
// =====================================================================================
#define GSTAGES 3
#define GEMM_SMEM (GSTAGES * 16384)

__global__ __launch_bounds__(256, 2) void gemm_kernel(
    const bf16* __restrict__ Ah, const bf16* __restrict__ Al,
    const bf16* __restrict__ Bh, const bf16* __restrict__ Bl,
    float* __restrict__ Cf, int lda, int ldb, int ldc, int M, int N, int K) {
    extern __shared__ __align__(16) unsigned short sm[];
    unsigned smBase = smem_u32(sm);
    const int tid = threadIdx.x;
    const int m0 = blockIdx.y * 128, n0 = blockIdx.x * 128;
    const int aRow = tid >> 1, aK = (tid & 1) * 8;
    const int physSt = (aK >> 3) ^ ((aRow >> 2) & 1);
    const unsigned stOff = aRow * 32 + physSt * 16;   // byte offset within one 4KB array
    const bf16* ApH = Ah + (size_t)(m0 + aRow) * lda + aK;
    const bf16* ApL = Al + (size_t)(m0 + aRow) * lda + aK;
    const int gn = n0 + aRow;
    const unsigned bBytes = (gn < N) ? 16u : 0u;
    const int gnc = (gn < N) ? gn : (N - 1);
    const bf16* BpH = Bh + (size_t)gnc * ldb + aK;
    const bf16* BpL = Bl + (size_t)gnc * ldb + aK;

    const int lane = tid & 31, warp = tid >> 5;
    const int g = lane >> 2, t = lane & 3;
    const int wM = (warp >> 2) * 64, wN = (warp & 3) * 32;
    const int lr = lane & 15, kc = lane >> 4;
    unsigned offA[4], offB[2];
#pragma unroll
    for (int mt = 0; mt < 4; mt++) {
        int r = wM + mt * 16 + lr;
        int ph = kc ^ ((r >> 2) & 1);
        offA[mt] = r * 32 + ph * 16;
    }
#pragma unroll
    for (int p = 0; p < 2; p++) {
        int r = wN + p * 16 + lr;
        int ph = kc ^ ((r >> 2) & 1);
        offB[p] = 2 * 4096 + r * 32 + ph * 16;
    }

    float acc[4][4][4];
#pragma unroll
    for (int i = 0; i < 4; i++)
#pragma unroll
        for (int j = 0; j < 4; j++)
#pragma unroll
            for (int r = 0; r < 4; r++) acc[i][j][r] = 0.f;

    const int nT = K >> 4;
    auto LOADA = [&](int stage, int k0) {
        unsigned d = smBase + stage * 16384 + stOff;
        cp16(d, ApH + k0, 16u);
        cp16(d + 4096, ApL + k0, 16u);
        cp16(d + 8192, BpH + k0, bBytes);
        cp16(d + 12288, BpL + k0, bBytes);
        CP_COMMIT();
    };

    LOADA(0, 0);
    if (nT > 1) LOADA(1, 16);
    int stage = 0;
    for (int tt = 0; tt < nT; ++tt) {
        CP_WAIT1();
        __syncthreads();
        if (tt + 2 < nT) {
            int ns = stage + 2;
            if (ns >= GSTAGES) ns -= GSTAGES;
            LOADA(ns, (tt + 2) << 4);
        }
        unsigned bo = smBase + stage * 16384;
        unsigned a_h[4][4], a_l[4][4], b_h[2][4], b_l[2][4];
#pragma unroll
        for (int mt = 0; mt < 4; mt++) {
            ldsm4(bo + offA[mt], a_h[mt][0], a_h[mt][1], a_h[mt][2], a_h[mt][3]);
            ldsm4(bo + offA[mt] + 4096, a_l[mt][0], a_l[mt][1], a_l[mt][2], a_l[mt][3]);
        }
#pragma unroll
        for (int p = 0; p < 2; p++) {
            ldsm4(bo + offB[p], b_h[p][0], b_h[p][1], b_h[p][2], b_h[p][3]);
            ldsm4(bo + offB[p] + 4096, b_l[p][0], b_l[p][1], b_l[p][2], b_l[p][3]);
        }
#pragma unroll
        for (int mt = 0; mt < 4; mt++)
#pragma unroll
            for (int nt = 0; nt < 4; nt++) {
                int p = nt >> 1, od = nt & 1;
                mma3(acc[mt][nt], a_h[mt], a_l[mt], b_h[p][od], b_h[p][od + 2],
                     b_l[p][od], b_l[p][od + 2]);
            }
        if (++stage == GSTAGES) stage = 0;
    }
#pragma unroll
    for (int mt = 0; mt < 4; mt++) {
        int r = m0 + wM + mt * 16 + g;
#pragma unroll
        for (int nt = 0; nt < 4; nt++) {
            int c = n0 + wN + nt * 8 + 2 * t;
            if (c < N) {
                *(float2*)(Cf + (size_t)r * ldc + c) =
                    make_float2(acc[mt][nt][0], acc[mt][nt][1]);
                *(float2*)(Cf + (size_t)(r + 8) * ldc + c) =
                    make_float2(acc[mt][nt][2], acc[mt][nt][3]);
            }
        }
    }
}

// =====================================================================================
// Flash attention — per (q-tile 128, bn) block, online softmax, 3xBF16 mma.
// =====================================================================================
#define SK_OFF 0
#define SKL_OFF 11264
#define SV_OFF 22528
#define SVL_OFF 33408
#define FLASH_SMEM ((22528 + 21760) * 2)

__global__ __launch_bounds__(256, 1) void flash_kernel(
    const bf16* __restrict__ qH, const bf16* __restrict__ qL,
    const bf16* __restrict__ kH, const bf16* __restrict__ kL,
    const bf16* __restrict__ vH, const bf16* __restrict__ vL,
    bf16* __restrict__ attH, bf16* __restrict__ attL) {
    extern __shared__ __align__(16) unsigned short sm[];
    unsigned short* sKh = sm + SK_OFF;
    unsigned short* sKl = sm + SKL_OFF;
    unsigned short* sVh = sm + SV_OFF;
    unsigned short* sVl = sm + SVL_OFF;
    unsigned smBase = smem_u32(sm);

    const int tid = threadIdx.x;
    const int qt = blockIdx.x, bn = blockIdx.y;
    const int b = bn >> 4, n = bn & 15;
    const int lane = tid & 31, warp = tid >> 5;
    const int g = lane >> 2, t = lane & 3;
    const int lr = lane & 15, kh = lane >> 4;
    const int qRow0 = warp * 16;

    const size_t qkStride = (size_t)NHEADS * HPAD;
    const size_t qBase = ((size_t)(b * L + qt * 128) * NHEADS + n) * HPAD;
    const size_t kBase = ((size_t)(b * L) * NHEADS + n) * HPAD;
    const size_t vBase = ((size_t)bn * HPAD) * L;

#pragma unroll
    for (int i = 0; i < 5; i++) {
        int idx = tid + i * 256;
        int r = idx / 10, c8 = (idx % 10) * 8;
        size_t go = qBase + (size_t)r * qkStride + c8;
        *(uint4*)&sKh[r * 88 + c8] = *(const uint4*)(qH + go);
        *(uint4*)&sKl[r * 88 + c8] = *(const uint4*)(qL + go);
    }
    __syncthreads();
    unsigned qh[5][4], ql[5][4];
#pragma unroll
    for (int ch = 0; ch < 5; ch++) {
        unsigned a = smBase + ((qRow0 + lr) * 88 + ch * 16 + kh * 8) * 2;
        ldsm4(a, qh[ch][0], qh[ch][1], qh[ch][2], qh[ch][3]);
        ldsm4(a + SKL_OFF * 2, ql[ch][0], ql[ch][1], ql[ch][2], ql[ch][3]);
    }
    __syncthreads();

    float Oacc[10][4];
#pragma unroll
    for (int i = 0; i < 10; i++)
#pragma unroll
        for (int j = 0; j < 4; j++) Oacc[i][j] = 0.f;
    float mA = -1e30f, mB = -1e30f, lA = 0.f, lB = 0.f;

    for (int st = 0; st < 8; st++) {
#pragma unroll
        for (int i = 0; i < 5; i++) {
            int idx = tid + i * 256;
            int r = idx / 10, c8 = (idx % 10) * 8;
            size_t go = kBase + (size_t)(st * 128 + r) * qkStride + c8;
            *(uint4*)&sKh[r * 88 + c8] = *(const uint4*)(kH + go);
            *(uint4*)&sKl[r * 88 + c8] = *(const uint4*)(kL + go);
            int vr = idx / 16, vc = (idx % 16) * 8;
            size_t gv = vBase + (size_t)vr * L + st * 128 + vc;
            *(uint4*)&sVh[vr * 136 + vc] = *(const uint4*)(vH + gv);
            *(uint4*)&sVl[vr * 136 + vc] = *(const uint4*)(vL + gv);
        }
        __syncthreads();

        float sacc[16][4];
#pragma unroll
        for (int i = 0; i < 16; i++)
#pragma unroll
            for (int j = 0; j < 4; j++) sacc[i][j] = 0.f;
#pragma unroll
        for (int ch = 0; ch < 5; ch++) {
#pragma unroll
            for (int ng = 0; ng < 8; ng++) {
                unsigned a = smBase + ((ng * 16 + lr) * 88 + ch * 16 + kh * 8) * 2;
                unsigned h0, h1, h2, h3, l0, l1, l2, l3;
                ldsm4(a, h0, h1, h2, h3);
                ldsm4(a + SKL_OFF * 2, l0, l1, l2, l3);
                mma3(sacc[2 * ng], qh[ch], ql[ch], h0, h2, l0, l2);
                mma3(sacc[2 * ng + 1], qh[ch], ql[ch], h1, h3, l1, l3);
            }
        }

        float tmA = -1e30f, tmB = -1e30f;
#pragma unroll
        for (int i = 0; i < 16; i++) {
            tmA = fmaxf(tmA, fmaxf(sacc[i][0], sacc[i][1]));
            tmB = fmaxf(tmB, fmaxf(sacc[i][2], sacc[i][3]));
        }
        tmA = fmaxf(tmA, __shfl_xor_sync(0xffffffffu, tmA, 1));
        tmA = fmaxf(tmA, __shfl_xor_sync(0xffffffffu, tmA, 2));
        tmB = fmaxf(tmB, __shfl_xor_sync(0xffffffffu, tmB, 1));
        tmB = fmaxf(tmB, __shfl_xor_sync(0xffffffffu, tmB, 2));
        float mnA = fmaxf(mA, tmA), mnB = fmaxf(mB, tmB);
        float fA = __expf(mA - mnA), fB = __expf(mB - mnB);
        mA = mnA; mB = mnB;
        float sA = 0.f, sB = 0.f;
#pragma unroll
        for (int i = 0; i < 16; i++) {
            sacc[i][0] = __expf(sacc[i][0] - mnA);
            sacc[i][1] = __expf(sacc[i][1] - mnA);
            sacc[i][2] = __expf(sacc[i][2] - mnB);
            sacc[i][3] = __expf(sacc[i][3] - mnB);
            sA += sacc[i][0] + sacc[i][1];
            sB += sacc[i][2] + sacc[i][3];
        }
        sA += __shfl_xor_sync(0xffffffffu, sA, 1);
        sA += __shfl_xor_sync(0xffffffffu, sA, 2);
        sB += __shfl_xor_sync(0xffffffffu, sB, 1);
        sB += __shfl_xor_sync(0xffffffffu, sB, 2);
        lA = lA * fA + sA;
        lB = lB * fB + sB;
#pragma unroll
        for (int i = 0; i < 10; i++) {
            Oacc[i][0] *= fA; Oacc[i][1] *= fA;
            Oacc[i][2] *= fB; Oacc[i][3] *= fB;
        }

#pragma unroll
        for (int kc = 0; kc < 8; kc++) {
            unsigned ah[4], al[4];
            pack2(sacc[2 * kc][0], sacc[2 * kc][1], ah[0], al[0]);
            pack2(sacc[2 * kc][2], sacc[2 * kc][3], ah[1], al[1]);
            pack2(sacc[2 * kc + 1][0], sacc[2 * kc + 1][1], ah[2], al[2]);
            pack2(sacc[2 * kc + 1][2], sacc[2 * kc + 1][3], ah[3], al[3]);
#pragma unroll
            for (int vg = 0; vg < 5; vg++) {
                unsigned a = smBase + SV_OFF * 2 + ((vg * 16 + lr) * 136 + kc * 16 + kh * 8) * 2;
                unsigned h0, h1, h2, h3, l0, l1, l2, l3;
                ldsm4(a, h0, h1, h2, h3);
                ldsm4(a + (SVL_OFF - SV_OFF) * 2, l0, l1, l2, l3);
                mma3(Oacc[2 * vg], ah, al, h0, h2, l0, l2);
                mma3(Oacc[2 * vg + 1], ah, al, h1, h3, l1, l3);
            }
        }
        __syncthreads();
    }

    float invA = 1.f / lA, invB = 1.f / lB;
    int row0 = b * L + qt * 128 + qRow0 + g;
#pragma unroll
    for (int nt = 0; nt < 9; nt++) {
        int c = n * HDIM + nt * 8 + 2 * t;
        size_t i0 = (size_t)row0 * DIM + c;
        size_t i1 = (size_t)(row0 + 8) * DIM + c;
        splitStore(Oacc[nt][0] * invA, attH, attL, i0);
        splitStore(Oacc[nt][1] * invA, attH, attL, i0 + 1);
        splitStore(Oacc[nt][2] * invB, attH, attL, i1);
        splitStore(Oacc[nt][3] * invB, attH, attL, i1 + 1);
    }
}

// ---------------- patchify ----------------
__global__ void patchify_kernel(const float* __restrict__ img, bf16* __restrict__ PH,
                                bf16* __restrict__ PL) {
    int idx = blockIdx.x * blockDim.x + threadIdx.x;
    if (idx >= BL * PATCHD) return;
    int bl = idx / PATCHD, j = idx % PATCHD;
    int b = bl >> 10, l = bl & 1023;
    int gy = l >> 5, gx = l & 31;
    int py = j / 48, r = j % 48;
    int px = r / 3, c = r % 3;
    int row = gy * 16 + py, col = gx * 16 + px;
    float v = 2.0f * img[(((size_t)b * 512 + row) * 512 + col) * 3 + c] - 1.0f;
    splitStore(v, PH, PL, idx);
}

// ---------------- pos-emb add ----------------
__global__ void add_posemb_kernel(float* __restrict__ x, const float* __restrict__ pe) {
    int idx = blockIdx.x * blockDim.x + threadIdx.x;
    if (idx >= BL * DIM) return;
    int bl = idx / DIM, d = idx % DIM;
    int l = bl & 1023;
    int posx = l & 31, posy = l >> 5;
    x[idx] += pe[(size_t)(posx * 2 + 0) * DIM + d] + pe[(size_t)(posy * 2 + 1) * DIM + d];
}

// ---------------- row RMSNorm -> hi/lo bf16 ----------------
__global__ void rmsnorm_kernel(const float* __restrict__ in, const float* __restrict__ scale,
                               bf16* __restrict__ outH, bf16* __restrict__ outL) {
    int row = blockIdx.x;
    const float* p = in + (size_t)row * DIM;
    float s = 0.f;
    for (int i = threadIdx.x; i < DIM; i += 256) { float v = p[i]; s += v * v; }
    __shared__ float red[256];
    red[threadIdx.x] = s; __syncthreads();
    for (int st = 128; st > 0; st >>= 1) {
        if (threadIdx.x < st) red[threadIdx.x] += red[threadIdx.x + st];
        __syncthreads();
    }
    float rs = rsqrtf(red[0] / (float)DIM + EPS);
    for (int i = threadIdx.x; i < DIM; i += 256)
        splitStore(p[i] * rs * (1.f + scale[i]), outH, outL, (size_t)row * DIM + i);
}

// ---------------- residual add of RMSNormed branch ----------------
__global__ void resid_rms_add_kernel(float* __restrict__ x, const float* __restrict__ o,
                                     const float* __restrict__ scale) {
    int row = blockIdx.x;
    const float* p = o + (size_t)row * DIM;
    float s = 0.f;
    for (int i = threadIdx.x; i < DIM; i += 256) { float v = p[i]; s += v * v; }
    __shared__ float red[256];
    red[threadIdx.x] = s; __syncthreads();
    for (int st = 128; st > 0; st >>= 1) {
        if (threadIdx.x < st) red[threadIdx.x] += red[threadIdx.x + st];
        __syncthreads();
    }
    float rs = rsqrtf(red[0] / (float)DIM + EPS);
    for (int i = threadIdx.x; i < DIM; i += 256)
        x[(size_t)row * DIM + i] += p[i] * rs * (1.f + scale[i]);
}

// ---------------- per-head RMS (+2D RoPE) from strided src -> padded hi/lo or V-T --------
__global__ void head_finish_kernel(const float* __restrict__ src, int srcld,
                                   const float* __restrict__ scale,
                                   bf16* __restrict__ outH, bf16* __restrict__ outL,
                                   int do_rope, int v_mode, float premul) {
    int warp = threadIdx.x >> 5, lane = threadIdx.x & 31;
    int item = blockIdx.x * 8 + warp;
    int token = item >> 4;
    int head = item & 15;
    const float* p = src + (size_t)token * srcld + head * HDIM;
    float v0 = p[lane];
    float v1 = p[lane + 32];
    float v2 = (lane < 8) ? p[lane + 64] : 0.f;
    float s = v0 * v0 + v1 * v1 + v2 * v2;
#pragma unroll
    for (int off = 16; off; off >>= 1) s += __shfl_xor_sync(0xffffffffu, s, off);
    float rs = rsqrtf(s / (float)HDIM + EPS) * premul;
    __shared__ float buf[8][HDIM];
    buf[warp][lane] = v0 * rs * (1.f + scale[lane]);
    buf[warp][lane + 32] = v1 * rs * (1.f + scale[lane + 32]);
    if (lane < 8) buf[warp][lane + 64] = v2 * rs * (1.f + scale[lane + 64]);
    __syncwarp();
    if (do_rope) {
        int l = token & 1023;
        float posx = (float)(l & 31), posy = (float)(l >> 5);
        for (int pp = lane; pp < 36; pp += 32) {
            int j = (pp < 18) ? pp : (pp - 18);
            float pos = (pp < 18) ? posx : posy;
            int d1 = (pp < 18) ? pp : (pp + 18);
            int d2 = d1 + 18;
            float ts = powf(100.f, (float)j / 18.f);
            float ang = pos / ts;
            float sn, cs;
            sincosf(ang, &sn, &cs);
            float a = buf[warp][d1], b2 = buf[warp][d2];
            buf[warp][d1] = a * cs - b2 * sn;
            buf[warp][d2] = b2 * cs + a * sn;
        }
        __syncwarp();
    }
    if (!v_mode) {
        size_t base = ((size_t)token * NHEADS + head) * HPAD;
        splitStore(buf[warp][lane], outH, outL, base + lane);
        splitStore(buf[warp][lane + 32], outH, outL, base + lane + 32);
        if (lane < 8) splitStore(buf[warp][lane + 64], outH, outL, base + lane + 64);
    } else {
        int b = token >> 10, l = token & 1023;
        size_t base = ((size_t)(b * NHEADS + head) * HPAD) * L + l;
        splitStore(buf[warp][lane], outH, outL, base + (size_t)lane * L);
        splitStore(buf[warp][lane + 32], outH, outL, base + (size_t)(lane + 32) * L);
        if (lane < 8) splitStore(buf[warp][lane + 64], outH, outL, base + (size_t)(lane + 64) * L);
    }
}

// ---------------- GeGLU from fused gateup -> hi/lo bf16 (K-padded) ----------------
__global__ void geglu_kernel(const float* __restrict__ gu, bf16* __restrict__ gH,
                             bf16* __restrict__ gL) {
    int idx = blockIdx.x * blockDim.x + threadIdx.x;
    if (idx >= BL * FF) return;
    int row = idx / FF, col = idx % FF;
    float g = gu[(size_t)row * GUD + col];
    float u = gu[(size_t)row * GUD + FF + col];
    float t = 0.7978845608028654f * (g + 0.044715f * g * g * g);
    splitStore(0.5f * g * (1.f + tanhf(t)) * u, gH, gL, (size_t)row * FF_PAD + col);
}

// ---------------- final ----------------
__global__ void final_kernel(const float* __restrict__ x, const float* __restrict__ bias,
                             const float* __restrict__ scl, float* __restrict__ out) {
    int idx = blockIdx.x * blockDim.x + threadIdx.x;
    if (idx >= BL * DIM) return;
    int d = idx % DIM;
    out[idx] = (x[idx] * 33.941125496954285f - bias[d]) * scl[d];
}

// ---------------- launcher ----------------
extern "C" void kernel_launch(void* const* d_in, const int* in_sizes, int n_in,
                              void* d_out, int out_size) {
    const float* inputs    = (const float*)d_in[0];
    const float* Wp        = (const float*)d_in[1];
    const float* posemb    = (const float*)d_in[2];
    const float* Wq        = (const float*)d_in[3];
    const float* Wk        = (const float*)d_in[4];
    const float* Wv        = (const float*)d_in[5];
    const float* Wo        = (const float*)d_in[6];
    const float* Wg        = (const float*)d_in[7];
    const float* Wu        = (const float*)d_in[8];
    const float* Wd        = (const float*)d_in[9];
    const float* qn        = (const float*)d_in[10];
    const float* kn        = (const float*)d_in[11];
    const float* vn        = (const float*)d_in[12];
    const float* pre_attn  = (const float*)d_in[13];
    const float* post_attn = (const float*)d_in[14];
    const float* pre_ffw   = (const float*)d_in[15];
    const float* post_ffw  = (const float*)d_in[16];
    const float* std_bias  = (const float*)d_in[17];
    const float* std_scale = (const float*)d_in[18];
    float* out = (float*)d_out;

    float *x, *qkv, *o, *gateup;
    cudaGetSymbolAddress((void**)&x, g_x);
    cudaGetSymbolAddress((void**)&qkv, g_qkv);
    cudaGetSymbolAddress((void**)&o, g_o);
    cudaGetSymbolAddress((void**)&gateup, g_gateup);
    bf16 *patH, *patL, *hH, *hL, *qpH, *qpL, *kpH, *kpL, *vtH, *vtL, *attH, *attL, *gH, *gL;
    cudaGetSymbolAddress((void**)&patH, g_patH); cudaGetSymbolAddress((void**)&patL, g_patL);
    cudaGetSymbolAddress((void**)&hH, g_hH);     cudaGetSymbolAddress((void**)&hL, g_hL);
    cudaGetSymbolAddress((void**)&qpH, g_qpH);   cudaGetSymbolAddress((void**)&qpL, g_qpL);
    cudaGetSymbolAddress((void**)&kpH, g_kpH);   cudaGetSymbolAddress((void**)&kpL, g_kpL);
    cudaGetSymbolAddress((void**)&vtH, g_vtH);   cudaGetSymbolAddress((void**)&vtL, g_vtL);
    cudaGetSymbolAddress((void**)&attH, g_attH); cudaGetSymbolAddress((void**)&attL, g_attL);
    cudaGetSymbolAddress((void**)&gH, g_gH);     cudaGetSymbolAddress((void**)&gL, g_gL);
    bf16 *WpH, *WpL, *WqkvH, *WqkvL, *WoH, *WoL, *WguH, *WguL, *WdH, *WdL;
    cudaGetSymbolAddress((void**)&WpH, g_WpH);     cudaGetSymbolAddress((void**)&WpL, g_WpL);
    cudaGetSymbolAddress((void**)&WqkvH, g_WqkvH); cudaGetSymbolAddress((void**)&WqkvL, g_WqkvL);
    cudaGetSymbolAddress((void**)&WoH, g_WoH);     cudaGetSymbolAddress((void**)&WoL, g_WoL);
    cudaGetSymbolAddress((void**)&WguH, g_WguH);   cudaGetSymbolAddress((void**)&WguL, g_WguL);
    cudaGetSymbolAddress((void**)&WdH, g_WdH);     cudaGetSymbolAddress((void**)&WdL, g_WdL);

    const float qk_scale = 0.11785113019775793f;  // 1/sqrt(72)
    dim3 tb(32, 8);

    static bool attr_set = false;
    if (!attr_set) {
        cudaFuncSetAttribute(flash_kernel, cudaFuncAttributeMaxDynamicSharedMemorySize,
                             FLASH_SMEM);
        cudaFuncSetAttribute(gemm_kernel, cudaFuncAttributeMaxDynamicSharedMemorySize,
                             GEMM_SMEM);
        attr_set = true;
    }

    // ---- weight prepack (transpose + hi/lo split, fused layouts) ----
    prepack_kernel<<<dim3((DIM + 31) / 32, (PATCHD + 31) / 32), tb>>>(Wp, WpH, WpL,
                                                                      PATCHD, DIM, PATCHD);
    for (int i = 0; i < NLAYERS; i++) {
        size_t so = (size_t)i * DIM * DIM;
        size_t qo = (size_t)i * QKVD * DIM;
        prepack_kernel<<<dim3(36, 36), tb>>>(Wq + so, WqkvH + qo, WqkvL + qo, DIM, DIM, DIM);
        prepack_kernel<<<dim3(36, 36), tb>>>(Wk + so, WqkvH + qo + (size_t)DIM * DIM,
                                             WqkvL + qo + (size_t)DIM * DIM, DIM, DIM, DIM);
        prepack_kernel<<<dim3(36, 36), tb>>>(Wv + so, WqkvH + qo + 2 * (size_t)DIM * DIM,
                                             WqkvL + qo + 2 * (size_t)DIM * DIM, DIM, DIM, DIM);
        prepack_kernel<<<dim3(36, 36), tb>>>(Wo + so, WoH + so, WoL + so, DIM, DIM, DIM);
        size_t fo = (size_t)i * DIM * FF;
        size_t go = (size_t)i * GUD * DIM;
        size_t fp = (size_t)i * DIM * FF_PAD;
        prepack_kernel<<<dim3((FF + 31) / 32, 36), tb>>>(Wg + fo, WguH + go, WguL + go,
                                                         DIM, FF, DIM);
        prepack_kernel<<<dim3((FF + 31) / 32, 36), tb>>>(Wu + fo, WguH + go + (size_t)FF * DIM,
                                                         WguL + go + (size_t)FF * DIM,
                                                         DIM, FF, DIM);
        prepack_kernel<<<dim3(36, (FF + 31) / 32), tb>>>(Wd + fo, WdH + fp, WdL + fp,
                                                         FF, DIM, FF_PAD);
    }

    // ---- entry ----
    patchify_kernel<<<(BL * PATCHD + 255) / 256, 256>>>(inputs, patH, patL);
    gemm_kernel<<<dim3(9, 16), 256, GEMM_SMEM>>>(patH, patL, WpH, WpL, x,
                                                 PATCHD, PATCHD, DIM, BL, DIM, PATCHD);
    add_posemb_kernel<<<(BL * DIM + 255) / 256, 256>>>(x, posemb);

    for (int i = 0; i < NLAYERS; i++) {
        size_t so = (size_t)i * DIM * DIM;
        size_t qo = (size_t)i * QKVD * DIM;
        size_t go = (size_t)i * GUD * DIM;
        size_t fp = (size_t)i * DIM * FF_PAD;

        // attention
        rmsnorm_kernel<<<BL, 256>>>(x, pre_attn + i * DIM, hH, hL);
        gemm_kernel<<<dim3(27, 16), 256, GEMM_SMEM>>>(hH, hL, WqkvH + qo, WqkvL + qo, qkv,
                                                      DIM, DIM, QKVD, BL, QKVD, DIM);
        head_finish_kernel<<<BL * NHEADS / 8, 256>>>(qkv, QKVD, qn + i * HDIM,
                                                     qpH, qpL, 1, 0, qk_scale);
        head_finish_kernel<<<BL * NHEADS / 8, 256>>>(qkv + DIM, QKVD, kn + i * HDIM,
                                                     kpH, kpL, 1, 0, 1.f);
        head_finish_kernel<<<BL * NHEADS / 8, 256>>>(qkv + 2 * DIM, QKVD, vn + i * HDIM,
                                                     vtH, vtL, 0, 1, 1.f);
        flash_kernel<<<dim3(8, 32), 256, FLASH_SMEM>>>(qpH, qpL, kpH, kpL, vtH, vtL,
                                                       attH, attL);
        gemm_kernel<<<dim3(9, 16), 256, GEMM_SMEM>>>(attH, attL, WoH + so, WoL + so, o,
                                                     DIM, DIM, DIM, BL, DIM, DIM);
        resid_rms_add_kernel<<<BL, 256>>>(x, o, post_attn + i * DIM);

        // GeGLU MLP
        rmsnorm_kernel<<<BL, 256>>>(x, pre_ffw + i * DIM, hH, hL);
        gemm_kernel<<<dim3(68, 16), 256, GEMM_SMEM>>>(hH, hL, WguH + go, WguL + go, gateup,
                                                      DIM, DIM, GUD, BL, GUD, DIM);
        geglu_kernel<<<(BL * FF + 255) / 256, 256>>>(gateup, gH, gL);
        gemm_kernel<<<dim3(9, 16), 256, GEMM_SMEM>>>(gH, gL, WdH + fp, WdL + fp, o,
                                                     FF_PAD, FF_PAD, DIM, BL, DIM, FF_PAD);
        resid_rms_add_kernel<<<BL, 256>>>(x, o, post_ffw + i * DIM);
    }

    // exit
    final_kernel<<<(BL * DIM + 255) / 256, 256>>>(x, std_bias, std_scale, out);
}

// round 11
// speedup vs baseline: 1.0490x; 1.0490x over previous
#include <cuda_runtime.h>
#include <cuda_bf16.h>
#include <math.h>

#define BATCH 2
#define L 1024
#define BL 2048
#define DIM 1152
#define QKVD 3456          // 3*DIM
#define NHEADS 16
#define HDIM 72
#define HPAD 80
#define FF 4304
#define FF_PAD 4352
#define GUD 8608           // 2*FF
#define NLAYERS 4
#define PATCHD 768
#define EPS 1e-6f

typedef __nv_bfloat16 bf16;

// ---------------- f32 scratch ----------------
__device__ float g_x[BL * DIM];
__device__ float g_qkv[(size_t)BL * QKVD];
__device__ float g_o[BL * DIM];
__device__ float g_gateup[(size_t)BL * GUD];

// ---------------- bf16 hi/lo activation scratch ----------------
__device__ bf16 g_patH[BL * PATCHD], g_patL[BL * PATCHD];
__device__ bf16 g_hH[BL * DIM], g_hL[BL * DIM];
__device__ bf16 g_qpH[BL * NHEADS * HPAD], g_qpL[BL * NHEADS * HPAD];
__device__ bf16 g_kpH[BL * NHEADS * HPAD], g_kpL[BL * NHEADS * HPAD];
__device__ bf16 g_vtH[BATCH * NHEADS * HPAD * L], g_vtL[BATCH * NHEADS * HPAD * L];
__device__ bf16 g_attH[BL * DIM], g_attL[BL * DIM];
__device__ bf16 g_gH[(size_t)BL * FF_PAD], g_gL[(size_t)BL * FF_PAD];

// ---------------- pre-split transposed weights [N][K] ----------------
__device__ bf16 g_WpH[DIM * PATCHD], g_WpL[DIM * PATCHD];
__device__ bf16 g_WqkvH[(size_t)NLAYERS * QKVD * DIM], g_WqkvL[(size_t)NLAYERS * QKVD * DIM];
__device__ bf16 g_WoH[NLAYERS * DIM * DIM], g_WoL[NLAYERS * DIM * DIM];
__device__ bf16 g_WguH[(size_t)NLAYERS * GUD * DIM], g_WguL[(size_t)NLAYERS * GUD * DIM];
__device__ bf16 g_WdH[(size_t)NLAYERS * DIM * FF_PAD], g_WdL[(size_t)NLAYERS * DIM * FF_PAD];

__device__ __forceinline__ void splitStore(float v, bf16* H, bf16* Lo, size_t idx) {
    bf16 h = __float2bfloat16(v);
    H[idx] = h;
    Lo[idx] = __float2bfloat16(v - __bfloat162float(h));
}
__device__ __forceinline__ unsigned smem_u32(const void* p) {
    unsigned a;
    asm("{ .reg .u64 t; cvta.to.shared.u64 t, %1; cvt.u32.u64 %0, t; }" : "=r"(a) : "l"(p));
    return a;
}
__device__ __forceinline__ void mma_bf16(float c[4], const unsigned a[4], unsigned b0,
                                         unsigned b1) {
    asm volatile(
        "mma.sync.aligned.m16n8k16.row.col.f32.bf16.bf16.f32 "
        "{%0,%1,%2,%3}, {%4,%5,%6,%7}, {%8,%9}, {%0,%1,%2,%3};"
        : "+f"(c[0]), "+f"(c[1]), "+f"(c[2]), "+f"(c[3])
        : "r"(a[0]), "r"(a[1]), "r"(a[2]), "r"(a[3]), "r"(b0), "r"(b1));
}
__device__ __forceinline__ void mma3(float c[4], const unsigned ah[4], const unsigned al[4],
                                     unsigned bh0, unsigned bh1, unsigned bl0, unsigned bl1) {
    mma_bf16(c, ah, bh0, bh1);
    mma_bf16(c, ah, bl0, bl1);
    mma_bf16(c, al, bh0, bh1);
}
__device__ __forceinline__ void ldsm4(unsigned addr, unsigned& r0, unsigned& r1, unsigned& r2,
                                      unsigned& r3) {
    asm volatile("ldmatrix.sync.aligned.m8n8.x4.shared.b16 {%0,%1,%2,%3}, [%4];"
                 : "=r"(r0), "=r"(r1), "=r"(r2), "=r"(r3)
                 : "r"(addr));
}
__device__ __forceinline__ void pack2(float x, float y, unsigned& hi, unsigned& lo) {
    __nv_bfloat162 h = __floats2bfloat162_rn(x, y);
    __nv_bfloat162 l = __floats2bfloat162_rn(x - __low2float(h), y - __high2float(h));
    hi = *reinterpret_cast<unsigned*>(&h);
    lo = *reinterpret_cast<unsigned*>(&l);
}
__device__ __forceinline__ void cp16(unsigned dst, const void* src, unsigned nbytes) {
    asm volatile("cp.async.cg.shared.global [%0], [%1], 16, %2;"
                 :: "r"(dst), "l"(src), "r"(nbytes) : "memory");
}
#define CP_COMMIT() asm volatile("cp.async.commit_group;" ::: "memory")
#define CP_WAIT1()  asm volatile("cp.async.wait_group 1;" ::: "memory")

// =====================================================================================
// prepack: transpose W[K][N] -> hi/lo bf16 [N][ldo] (k-contiguous)
// =====================================================================================
__global__ void prepack_kernel(const float* __restrict__ W, bf16* __restrict__ H,
                               bf16* __restrict__ Lo, int K, int N, int ldo) {
    __shared__ float t[32][33];
    int tx = threadIdx.x, ty = threadIdx.y;
    int n0 = blockIdx.x * 32, k0 = blockIdx.y * 32;
#pragma unroll
    for (int j = 0; j < 4; j++) {
        int k = k0 + ty + j * 8, n = n0 + tx;
        if (k < K && n < N) t[ty + j * 8][tx] = W[(size_t)k * N + n];
    }
    __syncthreads();
#pragma unroll
    for (int j = 0; j < 4; j++) {
        int n = n0 + ty + j * 8, k = k0 + tx;
        if (k < K && n < N) splitStore(t[tx][ty + j * 8], H, Lo, (size_t)n * ldo + k);
    }
}

// =====================================================================================
// NT tensor-core GEMM (3xBF16, cp.async 3-stage pipeline, ldmatrix consumer)
// =====================================================================================
#define GSTAGES 3
#define GEMM_SMEM (GSTAGES * 16384)

__global__ __launch_bounds__(256, 2) void gemm_kernel(
    const bf16* __restrict__ Ah, const bf16* __restrict__ Al,
    const bf16* __restrict__ Bh, const bf16* __restrict__ Bl,
    float* __restrict__ Cf, int lda, int ldb, int ldc, int M, int N, int K) {
    extern __shared__ __align__(16) unsigned short sm[];
    unsigned smBase = smem_u32(sm);
    const int tid = threadIdx.x;
    const int m0 = blockIdx.y * 128, n0 = blockIdx.x * 128;
    const int aRow = tid >> 1, aK = (tid & 1) * 8;
    const int physSt = (aK >> 3) ^ ((aRow >> 2) & 1);
    const unsigned stOff = aRow * 32 + physSt * 16;
    const bf16* ApH = Ah + (size_t)(m0 + aRow) * lda + aK;
    const bf16* ApL = Al + (size_t)(m0 + aRow) * lda + aK;
    const int gn = n0 + aRow;
    const unsigned bBytes = (gn < N) ? 16u : 0u;
    const int gnc = (gn < N) ? gn : (N - 1);
    const bf16* BpH = Bh + (size_t)gnc * ldb + aK;
    const bf16* BpL = Bl + (size_t)gnc * ldb + aK;

    const int lane = tid & 31, warp = tid >> 5;
    const int g = lane >> 2, t = lane & 3;
    const int wM = (warp >> 2) * 64, wN = (warp & 3) * 32;
    const int lr = lane & 15, kc = lane >> 4;
    unsigned offA[4], offB[2];
#pragma unroll
    for (int mt = 0; mt < 4; mt++) {
        int r = wM + mt * 16 + lr;
        int ph = kc ^ ((r >> 2) & 1);
        offA[mt] = r * 32 + ph * 16;
    }
#pragma unroll
    for (int p = 0; p < 2; p++) {
        int r = wN + p * 16 + lr;
        int ph = kc ^ ((r >> 2) & 1);
        offB[p] = 2 * 4096 + r * 32 + ph * 16;
    }

    float acc[4][4][4];
#pragma unroll
    for (int i = 0; i < 4; i++)
#pragma unroll
        for (int j = 0; j < 4; j++)
#pragma unroll
            for (int r = 0; r < 4; r++) acc[i][j][r] = 0.f;

    const int nT = K >> 4;
    auto LOADA = [&](int stage, int k0) {
        unsigned d = smBase + stage * 16384 + stOff;
        cp16(d, ApH + k0, 16u);
        cp16(d + 4096, ApL + k0, 16u);
        cp16(d + 8192, BpH + k0, bBytes);
        cp16(d + 12288, BpL + k0, bBytes);
        CP_COMMIT();
    };

    LOADA(0, 0);
    if (nT > 1) LOADA(1, 16);
    int stage = 0;
    for (int tt = 0; tt < nT; ++tt) {
        CP_WAIT1();
        __syncthreads();
        if (tt + 2 < nT) {
            int ns = stage + 2;
            if (ns >= GSTAGES) ns -= GSTAGES;
            LOADA(ns, (tt + 2) << 4);
        }
        unsigned bo = smBase + stage * 16384;
        unsigned a_h[4][4], a_l[4][4], b_h[2][4], b_l[2][4];
#pragma unroll
        for (int mt = 0; mt < 4; mt++) {
            ldsm4(bo + offA[mt], a_h[mt][0], a_h[mt][1], a_h[mt][2], a_h[mt][3]);
            ldsm4(bo + offA[mt] + 4096, a_l[mt][0], a_l[mt][1], a_l[mt][2], a_l[mt][3]);
        }
#pragma unroll
        for (int p = 0; p < 2; p++) {
            ldsm4(bo + offB[p], b_h[p][0], b_h[p][1], b_h[p][2], b_h[p][3]);
            ldsm4(bo + offB[p] + 4096, b_l[p][0], b_l[p][1], b_l[p][2], b_l[p][3]);
        }
#pragma unroll
        for (int mt = 0; mt < 4; mt++)
#pragma unroll
            for (int nt = 0; nt < 4; nt++) {
                int p = nt >> 1, od = nt & 1;
                mma3(acc[mt][nt], a_h[mt], a_l[mt], b_h[p][od], b_h[p][od + 2],
                     b_l[p][od], b_l[p][od + 2]);
            }
        if (++stage == GSTAGES) stage = 0;
    }
#pragma unroll
    for (int mt = 0; mt < 4; mt++) {
        int r = m0 + wM + mt * 16 + g;
#pragma unroll
        for (int nt = 0; nt < 4; nt++) {
            int c = n0 + wN + nt * 8 + 2 * t;
            if (c < N) {
                *(float2*)(Cf + (size_t)r * ldc + c) =
                    make_float2(acc[mt][nt][0], acc[mt][nt][1]);
                *(float2*)(Cf + (size_t)(r + 8) * ldc + c) =
                    make_float2(acc[mt][nt][2], acc[mt][nt][3]);
            }
        }
    }
}

// =====================================================================================
// Flash attention — per (q-tile 128, bn) block, online softmax, 3xBF16 mma.
// =====================================================================================
#define SK_OFF 0
#define SKL_OFF 11264
#define SV_OFF 22528
#define SVL_OFF 33408
#define FLASH_SMEM ((22528 + 21760) * 2)

__global__ __launch_bounds__(256, 1) void flash_kernel(
    const bf16* __restrict__ qH, const bf16* __restrict__ qL,
    const bf16* __restrict__ kH, const bf16* __restrict__ kL,
    const bf16* __restrict__ vH, const bf16* __restrict__ vL,
    bf16* __restrict__ attH, bf16* __restrict__ attL) {
    extern __shared__ __align__(16) unsigned short sm[];
    unsigned short* sKh = sm + SK_OFF;
    unsigned short* sKl = sm + SKL_OFF;
    unsigned short* sVh = sm + SV_OFF;
    unsigned short* sVl = sm + SVL_OFF;
    unsigned smBase = smem_u32(sm);

    const int tid = threadIdx.x;
    const int qt = blockIdx.x, bn = blockIdx.y;
    const int b = bn >> 4, n = bn & 15;
    const int lane = tid & 31, warp = tid >> 5;
    const int g = lane >> 2, t = lane & 3;
    const int lr = lane & 15, kh = lane >> 4;
    const int qRow0 = warp * 16;

    const size_t qkStride = (size_t)NHEADS * HPAD;
    const size_t qBase = ((size_t)(b * L + qt * 128) * NHEADS + n) * HPAD;
    const size_t kBase = ((size_t)(b * L) * NHEADS + n) * HPAD;
    const size_t vBase = ((size_t)bn * HPAD) * L;

#pragma unroll
    for (int i = 0; i < 5; i++) {
        int idx = tid + i * 256;
        int r = idx / 10, c8 = (idx % 10) * 8;
        size_t go = qBase + (size_t)r * qkStride + c8;
        *(uint4*)&sKh[r * 88 + c8] = *(const uint4*)(qH + go);
        *(uint4*)&sKl[r * 88 + c8] = *(const uint4*)(qL + go);
    }
    __syncthreads();
    unsigned qh[5][4], ql[5][4];
#pragma unroll
    for (int ch = 0; ch < 5; ch++) {
        unsigned a = smBase + ((qRow0 + lr) * 88 + ch * 16 + kh * 8) * 2;
        ldsm4(a, qh[ch][0], qh[ch][1], qh[ch][2], qh[ch][3]);
        ldsm4(a + SKL_OFF * 2, ql[ch][0], ql[ch][1], ql[ch][2], ql[ch][3]);
    }
    __syncthreads();

    float Oacc[10][4];
#pragma unroll
    for (int i = 0; i < 10; i++)
#pragma unroll
        for (int j = 0; j < 4; j++) Oacc[i][j] = 0.f;
    float mA = -1e30f, mB = -1e30f, lA = 0.f, lB = 0.f;

    for (int st = 0; st < 8; st++) {
#pragma unroll
        for (int i = 0; i < 5; i++) {
            int idx = tid + i * 256;
            int r = idx / 10, c8 = (idx % 10) * 8;
            size_t go = kBase + (size_t)(st * 128 + r) * qkStride + c8;
            *(uint4*)&sKh[r * 88 + c8] = *(const uint4*)(kH + go);
            *(uint4*)&sKl[r * 88 + c8] = *(const uint4*)(kL + go);
            int vr = idx / 16, vc = (idx % 16) * 8;
            size_t gv = vBase + (size_t)vr * L + st * 128 + vc;
            *(uint4*)&sVh[vr * 136 + vc] = *(const uint4*)(vH + gv);
            *(uint4*)&sVl[vr * 136 + vc] = *(const uint4*)(vL + gv);
        }
        __syncthreads();

        float sacc[16][4];
#pragma unroll
        for (int i = 0; i < 16; i++)
#pragma unroll
            for (int j = 0; j < 4; j++) sacc[i][j] = 0.f;
#pragma unroll
        for (int ch = 0; ch < 5; ch++) {
#pragma unroll
            for (int ng = 0; ng < 8; ng++) {
                unsigned a = smBase + ((ng * 16 + lr) * 88 + ch * 16 + kh * 8) * 2;
                unsigned h0, h1, h2, h3, l0, l1, l2, l3;
                ldsm4(a, h0, h1, h2, h3);
                ldsm4(a + SKL_OFF * 2, l0, l1, l2, l3);
                mma3(sacc[2 * ng], qh[ch], ql[ch], h0, h2, l0, l2);
                mma3(sacc[2 * ng + 1], qh[ch], ql[ch], h1, h3, l1, l3);
            }
        }

        float tmA = -1e30f, tmB = -1e30f;
#pragma unroll
        for (int i = 0; i < 16; i++) {
            tmA = fmaxf(tmA, fmaxf(sacc[i][0], sacc[i][1]));
            tmB = fmaxf(tmB, fmaxf(sacc[i][2], sacc[i][3]));
        }
        tmA = fmaxf(tmA, __shfl_xor_sync(0xffffffffu, tmA, 1));
        tmA = fmaxf(tmA, __shfl_xor_sync(0xffffffffu, tmA, 2));
        tmB = fmaxf(tmB, __shfl_xor_sync(0xffffffffu, tmB, 1));
        tmB = fmaxf(tmB, __shfl_xor_sync(0xffffffffu, tmB, 2));
        float mnA = fmaxf(mA, tmA), mnB = fmaxf(mB, tmB);
        float fA = __expf(mA - mnA), fB = __expf(mB - mnB);
        mA = mnA; mB = mnB;
        float sA = 0.f, sB = 0.f;
#pragma unroll
        for (int i = 0; i < 16; i++) {
            sacc[i][0] = __expf(sacc[i][0] - mnA);
            sacc[i][1] = __expf(sacc[i][1] - mnA);
            sacc[i][2] = __expf(sacc[i][2] - mnB);
            sacc[i][3] = __expf(sacc[i][3] - mnB);
            sA += sacc[i][0] + sacc[i][1];
            sB += sacc[i][2] + sacc[i][3];
        }
        sA += __shfl_xor_sync(0xffffffffu, sA, 1);
        sA += __shfl_xor_sync(0xffffffffu, sA, 2);
        sB += __shfl_xor_sync(0xffffffffu, sB, 1);
        sB += __shfl_xor_sync(0xffffffffu, sB, 2);
        lA = lA * fA + sA;
        lB = lB * fB + sB;
#pragma unroll
        for (int i = 0; i < 10; i++) {
            Oacc[i][0] *= fA; Oacc[i][1] *= fA;
            Oacc[i][2] *= fB; Oacc[i][3] *= fB;
        }

#pragma unroll
        for (int kc = 0; kc < 8; kc++) {
            unsigned ah[4], al[4];
            pack2(sacc[2 * kc][0], sacc[2 * kc][1], ah[0], al[0]);
            pack2(sacc[2 * kc][2], sacc[2 * kc][3], ah[1], al[1]);
            pack2(sacc[2 * kc + 1][0], sacc[2 * kc + 1][1], ah[2], al[2]);
            pack2(sacc[2 * kc + 1][2], sacc[2 * kc + 1][3], ah[3], al[3]);
#pragma unroll
            for (int vg = 0; vg < 5; vg++) {
                unsigned a = smBase + SV_OFF * 2 + ((vg * 16 + lr) * 136 + kc * 16 + kh * 8) * 2;
                unsigned h0, h1, h2, h3, l0, l1, l2, l3;
                ldsm4(a, h0, h1, h2, h3);
                ldsm4(a + (SVL_OFF - SV_OFF) * 2, l0, l1, l2, l3);
                mma3(Oacc[2 * vg], ah, al, h0, h2, l0, l2);
                mma3(Oacc[2 * vg + 1], ah, al, h1, h3, l1, l3);
            }
        }
        __syncthreads();
    }

    float invA = 1.f / lA, invB = 1.f / lB;
    int row0 = b * L + qt * 128 + qRow0 + g;
#pragma unroll
    for (int nt = 0; nt < 9; nt++) {
        int c = n * HDIM + nt * 8 + 2 * t;
        size_t i0 = (size_t)row0 * DIM + c;
        size_t i1 = (size_t)(row0 + 8) * DIM + c;
        splitStore(Oacc[nt][0] * invA, attH, attL, i0);
        splitStore(Oacc[nt][1] * invA, attH, attL, i0 + 1);
        splitStore(Oacc[nt][2] * invB, attH, attL, i1);
        splitStore(Oacc[nt][3] * invB, attH, attL, i1 + 1);
    }
}

// ---------------- patchify ----------------
__global__ void patchify_kernel(const float* __restrict__ img, bf16* __restrict__ PH,
                                bf16* __restrict__ PL) {
    int idx = blockIdx.x * blockDim.x + threadIdx.x;
    if (idx >= BL * PATCHD) return;
    int bl = idx / PATCHD, j = idx % PATCHD;
    int b = bl >> 10, l = bl & 1023;
    int gy = l >> 5, gx = l & 31;
    int py = j / 48, r = j % 48;
    int px = r / 3, c = r % 3;
    int row = gy * 16 + py, col = gx * 16 + px;
    float v = 2.0f * img[(((size_t)b * 512 + row) * 512 + col) * 3 + c] - 1.0f;
    splitStore(v, PH, PL, idx);
}

// ---------------- pos-emb add ----------------
__global__ void add_posemb_kernel(float* __restrict__ x, const float* __restrict__ pe) {
    int idx = blockIdx.x * blockDim.x + threadIdx.x;
    if (idx >= BL * DIM) return;
    int bl = idx / DIM, d = idx % DIM;
    int l = bl & 1023;
    int posx = l & 31, posy = l >> 5;
    x[idx] += pe[(size_t)(posx * 2 + 0) * DIM + d] + pe[(size_t)(posy * 2 + 1) * DIM + d];
}

// ---------------- row RMSNorm -> hi/lo bf16 (layer-0 entry only) ----------------
__global__ void rmsnorm_kernel(const float* __restrict__ in, const float* __restrict__ scale,
                               bf16* __restrict__ outH, bf16* __restrict__ outL) {
    int row = blockIdx.x;
    const float* p = in + (size_t)row * DIM;
    float s = 0.f;
    for (int i = threadIdx.x; i < DIM; i += 256) { float v = p[i]; s += v * v; }
    __shared__ float red[256];
    red[threadIdx.x] = s; __syncthreads();
    for (int st = 128; st > 0; st >>= 1) {
        if (threadIdx.x < st) red[threadIdx.x] += red[threadIdx.x + st];
        __syncthreads();
    }
    float rs = rsqrtf(red[0] / (float)DIM + EPS);
    for (int i = threadIdx.x; i < DIM; i += 256)
        splitStore(p[i] * rs * (1.f + scale[i]), outH, outL, (size_t)row * DIM + i);
}

// ---------------- fused: x += rms(o)*(1+rsc); h = rms(x)*(1+nsc) -> hi/lo ----------------
__global__ void resid_rms_norm_kernel(float* __restrict__ x, const float* __restrict__ o,
                                      const float* __restrict__ rsc,
                                      const float* __restrict__ nsc,
                                      bf16* __restrict__ outH, bf16* __restrict__ outL) {
    int row = blockIdx.x;
    const float* po = o + (size_t)row * DIM;
    float* px = x + (size_t)row * DIM;
    float ov[5], xv[5];
    float s = 0.f;
#pragma unroll
    for (int j = 0; j < 5; j++) {
        int i = threadIdx.x + j * 256;
        if (i < DIM) { ov[j] = po[i]; xv[j] = px[i]; s += ov[j] * ov[j]; }
        else { ov[j] = 0.f; xv[j] = 0.f; }
    }
    __shared__ float red[256];
    red[threadIdx.x] = s; __syncthreads();
    for (int st = 128; st > 0; st >>= 1) {
        if (threadIdx.x < st) red[threadIdx.x] += red[threadIdx.x + st];
        __syncthreads();
    }
    float rs = rsqrtf(red[0] / (float)DIM + EPS);
    __syncthreads();
    float s2 = 0.f;
#pragma unroll
    for (int j = 0; j < 5; j++) {
        int i = threadIdx.x + j * 256;
        if (i < DIM) {
            xv[j] += ov[j] * rs * (1.f + rsc[i]);
            s2 += xv[j] * xv[j];
            px[i] = xv[j];
        }
    }
    red[threadIdx.x] = s2; __syncthreads();
    for (int st = 128; st > 0; st >>= 1) {
        if (threadIdx.x < st) red[threadIdx.x] += red[threadIdx.x + st];
        __syncthreads();
    }
    float rs2 = rsqrtf(red[0] / (float)DIM + EPS);
#pragma unroll
    for (int j = 0; j < 5; j++) {
        int i = threadIdx.x + j * 256;
        if (i < DIM)
            splitStore(xv[j] * rs2 * (1.f + nsc[i]), outH, outL, (size_t)row * DIM + i);
    }
}

// ---------------- fused: x += rms(o)*(1+rsc); out = (x*sqrtD - bias)*scale ----------------
__global__ void resid_final_kernel(const float* __restrict__ x, const float* __restrict__ o,
                                   const float* __restrict__ rsc,
                                   const float* __restrict__ bias,
                                   const float* __restrict__ scl, float* __restrict__ out) {
    int row = blockIdx.x;
    const float* po = o + (size_t)row * DIM;
    const float* px = x + (size_t)row * DIM;
    float ov[5];
    float s = 0.f;
#pragma unroll
    for (int j = 0; j < 5; j++) {
        int i = threadIdx.x + j * 256;
        ov[j] = (i < DIM) ? po[i] : 0.f;
        s += ov[j] * ov[j];
    }
    __shared__ float red[256];
    red[threadIdx.x] = s; __syncthreads();
    for (int st = 128; st > 0; st >>= 1) {
        if (threadIdx.x < st) red[threadIdx.x] += red[threadIdx.x + st];
        __syncthreads();
    }
    float rs = rsqrtf(red[0] / (float)DIM + EPS);
#pragma unroll
    for (int j = 0; j < 5; j++) {
        int i = threadIdx.x + j * 256;
        if (i < DIM) {
            float xn = px[i] + ov[j] * rs * (1.f + rsc[i]);
            out[(size_t)row * DIM + i] = (xn * 33.941125496954285f - bias[i]) * scl[i];
        }
    }
}

// ---------------- fused per-head RMS (+2D RoPE): blockIdx.y = 0:q 1:k 2:v ----------------
__global__ void head_finish_fused(const float* __restrict__ qkv,
                                  const float* __restrict__ qn, const float* __restrict__ kn,
                                  const float* __restrict__ vn,
                                  bf16* __restrict__ qpH, bf16* __restrict__ qpL,
                                  bf16* __restrict__ kpH, bf16* __restrict__ kpL,
                                  bf16* __restrict__ vtH, bf16* __restrict__ vtL,
                                  float qk_scale) {
    int sec = blockIdx.y;
    const float* scale = (sec == 0) ? qn : ((sec == 1) ? kn : vn);
    float premul = (sec == 0) ? qk_scale : 1.f;
    int warp = threadIdx.x >> 5, lane = threadIdx.x & 31;
    int item = blockIdx.x * 8 + warp;
    int token = item >> 4;
    int head = item & 15;
    const float* p = qkv + (size_t)token * QKVD + sec * DIM + head * HDIM;
    float v0 = p[lane];
    float v1 = p[lane + 32];
    float v2 = (lane < 8) ? p[lane + 64] : 0.f;
    float s = v0 * v0 + v1 * v1 + v2 * v2;
#pragma unroll
    for (int off = 16; off; off >>= 1) s += __shfl_xor_sync(0xffffffffu, s, off);
    float rs = rsqrtf(s / (float)HDIM + EPS) * premul;
    __shared__ float buf[8][HDIM];
    buf[warp][lane] = v0 * rs * (1.f + scale[lane]);
    buf[warp][lane + 32] = v1 * rs * (1.f + scale[lane + 32]);
    if (lane < 8) buf[warp][lane + 64] = v2 * rs * (1.f + scale[lane + 64]);
    __syncwarp();
    if (sec < 2) {
        int l = token & 1023;
        float posx = (float)(l & 31), posy = (float)(l >> 5);
        for (int pp = lane; pp < 36; pp += 32) {
            int j = (pp < 18) ? pp : (pp - 18);
            float pos = (pp < 18) ? posx : posy;
            int d1 = (pp < 18) ? pp : (pp + 18);
            int d2 = d1 + 18;
            float ts = powf(100.f, (float)j / 18.f);
            float ang = pos / ts;
            float sn, cs;
            sincosf(ang, &sn, &cs);
            float a = buf[warp][d1], b2 = buf[warp][d2];
            buf[warp][d1] = a * cs - b2 * sn;
            buf[warp][d2] = b2 * cs + a * sn;
        }
        __syncwarp();
    }
    if (sec < 2) {
        bf16* oH = (sec == 0) ? qpH : kpH;
        bf16* oL = (sec == 0) ? qpL : kpL;
        size_t base = ((size_t)token * NHEADS + head) * HPAD;
        splitStore(buf[warp][lane], oH, oL, base + lane);
        splitStore(buf[warp][lane + 32], oH, oL, base + lane + 32);
        if (lane < 8) splitStore(buf[warp][lane + 64], oH, oL, base + lane + 64);
    } else {
        int b = token >> 10, l = token & 1023;
        size_t base = ((size_t)(b * NHEADS + head) * HPAD) * L + l;
        splitStore(buf[warp][lane], vtH, vtL, base + (size_t)lane * L);
        splitStore(buf[warp][lane + 32], vtH, vtL, base + (size_t)(lane + 32) * L);
        if (lane < 8) splitStore(buf[warp][lane + 64], vtH, vtL, base + (size_t)(lane + 64) * L);
    }
}

// ---------------- GeGLU from fused gateup -> hi/lo bf16 (K-padded) ----------------
__global__ void geglu_kernel(const float* __restrict__ gu, bf16* __restrict__ gH,
                             bf16* __restrict__ gL) {
    int idx = blockIdx.x * blockDim.x + threadIdx.x;
    if (idx >= BL * FF) return;
    int row = idx / FF, col = idx % FF;
    float g = gu[(size_t)row * GUD + col];
    float u = gu[(size_t)row * GUD + FF + col];
    float t = 0.7978845608028654f * (g + 0.044715f * g * g * g);
    splitStore(0.5f * g * (1.f + tanhf(t)) * u, gH, gL, (size_t)row * FF_PAD + col);
}

// ---------------- launcher ----------------
extern "C" void kernel_launch(void* const* d_in, const int* in_sizes, int n_in,
                              void* d_out, int out_size) {
    const float* inputs    = (const float*)d_in[0];
    const float* Wp        = (const float*)d_in[1];
    const float* posemb    = (const float*)d_in[2];
    const float* Wq        = (const float*)d_in[3];
    const float* Wk        = (const float*)d_in[4];
    const float* Wv        = (const float*)d_in[5];
    const float* Wo        = (const float*)d_in[6];
    const float* Wg        = (const float*)d_in[7];
    const float* Wu        = (const float*)d_in[8];
    const float* Wd        = (const float*)d_in[9];
    const float* qn        = (const float*)d_in[10];
    const float* kn        = (const float*)d_in[11];
    const float* vn        = (const float*)d_in[12];
    const float* pre_attn  = (const float*)d_in[13];
    const float* post_attn = (const float*)d_in[14];
    const float* pre_ffw   = (const float*)d_in[15];
    const float* post_ffw  = (const float*)d_in[16];
    const float* std_bias  = (const float*)d_in[17];
    const float* std_scale = (const float*)d_in[18];
    float* out = (float*)d_out;

    float *x, *qkv, *o, *gateup;
    cudaGetSymbolAddress((void**)&x, g_x);
    cudaGetSymbolAddress((void**)&qkv, g_qkv);
    cudaGetSymbolAddress((void**)&o, g_o);
    cudaGetSymbolAddress((void**)&gateup, g_gateup);
    bf16 *patH, *patL, *hH, *hL, *qpH, *qpL, *kpH, *kpL, *vtH, *vtL, *attH, *attL, *gH, *gL;
    cudaGetSymbolAddress((void**)&patH, g_patH); cudaGetSymbolAddress((void**)&patL, g_patL);
    cudaGetSymbolAddress((void**)&hH, g_hH);     cudaGetSymbolAddress((void**)&hL, g_hL);
    cudaGetSymbolAddress((void**)&qpH, g_qpH);   cudaGetSymbolAddress((void**)&qpL, g_qpL);
    cudaGetSymbolAddress((void**)&kpH, g_kpH);   cudaGetSymbolAddress((void**)&kpL, g_kpL);
    cudaGetSymbolAddress((void**)&vtH, g_vtH);   cudaGetSymbolAddress((void**)&vtL, g_vtL);
    cudaGetSymbolAddress((void**)&attH, g_attH); cudaGetSymbolAddress((void**)&attL, g_attL);
    cudaGetSymbolAddress((void**)&gH, g_gH);     cudaGetSymbolAddress((void**)&gL, g_gL);
    bf16 *WpH, *WpL, *WqkvH, *WqkvL, *WoH, *WoL, *WguH, *WguL, *WdH, *WdL;
    cudaGetSymbolAddress((void**)&WpH, g_WpH);     cudaGetSymbolAddress((void**)&WpL, g_WpL);
    cudaGetSymbolAddress((void**)&WqkvH, g_WqkvH); cudaGetSymbolAddress((void**)&WqkvL, g_WqkvL);
    cudaGetSymbolAddress((void**)&WoH, g_WoH);     cudaGetSymbolAddress((void**)&WoL, g_WoL);
    cudaGetSymbolAddress((void**)&WguH, g_WguH);   cudaGetSymbolAddress((void**)&WguL, g_WguL);
    cudaGetSymbolAddress((void**)&WdH, g_WdH);     cudaGetSymbolAddress((void**)&WdL, g_WdL);

    const float qk_scale = 0.11785113019775793f;  // 1/sqrt(72)
    dim3 tb(32, 8);

    static cudaStream_t s2 = nullptr;
    static cudaEvent_t evFork, evWp, evL[NLAYERS];
    static bool attr_set = false;
    if (!attr_set) {
        cudaFuncSetAttribute(flash_kernel, cudaFuncAttributeMaxDynamicSharedMemorySize,
                             FLASH_SMEM);
        cudaFuncSetAttribute(gemm_kernel, cudaFuncAttributeMaxDynamicSharedMemorySize,
                             GEMM_SMEM);
        cudaStreamCreateWithFlags(&s2, cudaStreamNonBlocking);
        cudaEventCreateWithFlags(&evFork, cudaEventDisableTiming);
        cudaEventCreateWithFlags(&evWp, cudaEventDisableTiming);
        for (int i = 0; i < NLAYERS; i++)
            cudaEventCreateWithFlags(&evL[i], cudaEventDisableTiming);
        attr_set = true;
    }

    // ---- fork prepack stream ----
    cudaEventRecord(evFork, 0);
    cudaStreamWaitEvent(s2, evFork, 0);
    prepack_kernel<<<dim3((DIM + 31) / 32, (PATCHD + 31) / 32), tb, 0, s2>>>(
        Wp, WpH, WpL, PATCHD, DIM, PATCHD);
    cudaEventRecord(evWp, s2);
    for (int i = 0; i < NLAYERS; i++) {
        size_t so = (size_t)i * DIM * DIM;
        size_t qo = (size_t)i * QKVD * DIM;
        prepack_kernel<<<dim3(36, 36), tb, 0, s2>>>(Wq + so, WqkvH + qo, WqkvL + qo,
                                                    DIM, DIM, DIM);
        prepack_kernel<<<dim3(36, 36), tb, 0, s2>>>(Wk + so, WqkvH + qo + (size_t)DIM * DIM,
                                                    WqkvL + qo + (size_t)DIM * DIM,
                                                    DIM, DIM, DIM);
        prepack_kernel<<<dim3(36, 36), tb, 0, s2>>>(Wv + so, WqkvH + qo + 2 * (size_t)DIM * DIM,
                                                    WqkvL + qo + 2 * (size_t)DIM * DIM,
                                                    DIM, DIM, DIM);
        prepack_kernel<<<dim3(36, 36), tb, 0, s2>>>(Wo + so, WoH + so, WoL + so, DIM, DIM, DIM);
        size_t fo = (size_t)i * DIM * FF;
        size_t go = (size_t)i * GUD * DIM;
        size_t fp = (size_t)i * DIM * FF_PAD;
        prepack_kernel<<<dim3((FF + 31) / 32, 36), tb, 0, s2>>>(Wg + fo, WguH + go, WguL + go,
                                                                DIM, FF, DIM);
        prepack_kernel<<<dim3((FF + 31) / 32, 36), tb, 0, s2>>>(
            Wu + fo, WguH + go + (size_t)FF * DIM, WguL + go + (size_t)FF * DIM, DIM, FF, DIM);
        prepack_kernel<<<dim3(36, (FF + 31) / 32), tb, 0, s2>>>(Wd + fo, WdH + fp, WdL + fp,
                                                                FF, DIM, FF_PAD);
        cudaEventRecord(evL[i], s2);
    }

    // ---- entry ----
    patchify_kernel<<<(BL * PATCHD + 255) / 256, 256>>>(inputs, patH, patL);
    cudaStreamWaitEvent(0, evWp, 0);
    gemm_kernel<<<dim3(9, 16), 256, GEMM_SMEM>>>(patH, patL, WpH, WpL, x,
                                                 PATCHD, PATCHD, DIM, BL, DIM, PATCHD);
    add_posemb_kernel<<<(BL * DIM + 255) / 256, 256>>>(x, posemb);
    rmsnorm_kernel<<<BL, 256>>>(x, pre_attn, hH, hL);

    for (int i = 0; i < NLAYERS; i++) {
        size_t so = (size_t)i * DIM * DIM;
        size_t qo = (size_t)i * QKVD * DIM;
        size_t go = (size_t)i * GUD * DIM;
        size_t fp = (size_t)i * DIM * FF_PAD;

        cudaStreamWaitEvent(0, evL[i], 0);

        // attention
        gemm_kernel<<<dim3(27, 16), 256, GEMM_SMEM>>>(hH, hL, WqkvH + qo, WqkvL + qo, qkv,
                                                      DIM, DIM, QKVD, BL, QKVD, DIM);
        head_finish_fused<<<dim3(BL * NHEADS / 8, 3), 256>>>(qkv, qn + i * HDIM, kn + i * HDIM,
                                                             vn + i * HDIM, qpH, qpL, kpH, kpL,
                                                             vtH, vtL, qk_scale);
        flash_kernel<<<dim3(8, 32), 256, FLASH_SMEM>>>(qpH, qpL, kpH, kpL, vtH, vtL,
                                                       attH, attL);
        gemm_kernel<<<dim3(9, 16), 256, GEMM_SMEM>>>(attH, attL, WoH + so, WoL + so, o,
                                                     DIM, DIM, DIM, BL, DIM, DIM);
        resid_rms_norm_kernel<<<BL, 256>>>(x, o, post_attn + i * DIM, pre_ffw + i * DIM,
                                           hH, hL);

        // GeGLU MLP
        gemm_kernel<<<dim3(68, 16), 256, GEMM_SMEM>>>(hH, hL, WguH + go, WguL + go, gateup,
                                                      DIM, DIM, GUD, BL, GUD, DIM);
        geglu_kernel<<<(BL * FF + 255) / 256, 256>>>(gateup, gH, gL);
        gemm_kernel<<<dim3(9, 16), 256, GEMM_SMEM>>>(gH, gL, WdH + fp, WdL + fp, o,
                                                     FF_PAD, FF_PAD, DIM, BL, DIM, FF_PAD);
        if (i < NLAYERS - 1) {
            resid_rms_norm_kernel<<<BL, 256>>>(x, o, post_ffw + i * DIM,
                                               pre_attn + (i + 1) * DIM, hH, hL);
        } else {
            resid_final_kernel<<<BL, 256>>>(x, o, post_ffw + i * DIM, std_bias, std_scale,
                                            out);
        }
    }
}

// round 12
// speedup vs baseline: 1.3495x; 1.2865x over previous
#include <cuda_runtime.h>
#include <cuda_bf16.h>
#include <cuda_fp16.h>
#include <math.h>

#define BATCH 2
#define L 1024
#define BL 2048
#define DIM 1152
#define QKVD 3456          // 3*DIM
#define NHEADS 16
#define HDIM 72
#define HPAD 80
#define FF 4304
#define FF_PAD 4352
#define GUD 8608           // 2*FF interleaved (gate_j at 2j, up_j at 2j+1)
#define NLAYERS 4
#define PATCHD 768
#define EPS 1e-6f

typedef __nv_bfloat16 bf16;

// ---------------- f32 scratch ----------------
__device__ float g_x[BL * DIM];
__device__ float g_qkv[(size_t)BL * QKVD];
__device__ float g_o[BL * DIM];

// ---------------- fp16 hi/lo activation scratch (GEMM A operands) ----------------
__device__ __half g_patH[BL * PATCHD], g_patL[BL * PATCHD];
__device__ __half g_hH[BL * DIM], g_hL[BL * DIM];
__device__ __half g_attH[BL * DIM], g_attL[BL * DIM];
__device__ __half g_gH[(size_t)BL * FF_PAD], g_gL[(size_t)BL * FF_PAD];

// ---------------- bf16 hi/lo flash operands ----------------
__device__ bf16 g_qpH[BL * NHEADS * HPAD], g_qpL[BL * NHEADS * HPAD];
__device__ bf16 g_kpH[BL * NHEADS * HPAD], g_kpL[BL * NHEADS * HPAD];
__device__ bf16 g_vtH[BATCH * NHEADS * HPAD * L], g_vtL[BATCH * NHEADS * HPAD * L];

// ---------------- single-fp16 transposed weights [N][K] ----------------
__device__ __half g_WpH[DIM * PATCHD];
__device__ __half g_WqkvH[(size_t)NLAYERS * QKVD * DIM];
__device__ __half g_WoH[NLAYERS * DIM * DIM];
__device__ __half g_WguH[(size_t)NLAYERS * GUD * DIM];
__device__ __half g_WdH[(size_t)NLAYERS * DIM * FF_PAD];

__device__ __forceinline__ void splitStoreH(float v, __half* H, __half* Lo, size_t idx) {
    __half h = __float2half(v);
    H[idx] = h;
    Lo[idx] = __float2half(v - __half2float(h));
}
__device__ __forceinline__ void splitStoreB(float v, bf16* H, bf16* Lo, size_t idx) {
    bf16 h = __float2bfloat16(v);
    H[idx] = h;
    Lo[idx] = __float2bfloat16(v - __bfloat162float(h));
}
__device__ __forceinline__ unsigned smem_u32(const void* p) {
    unsigned a;
    asm("{ .reg .u64 t; cvta.to.shared.u64 t, %1; cvt.u32.u64 %0, t; }" : "=r"(a) : "l"(p));
    return a;
}
__device__ __forceinline__ void mma_f16(float c[4], const unsigned a[4], unsigned b0,
                                        unsigned b1) {
    asm volatile(
        "mma.sync.aligned.m16n8k16.row.col.f32.f16.f16.f32 "
        "{%0,%1,%2,%3}, {%4,%5,%6,%7}, {%8,%9}, {%0,%1,%2,%3};"
        : "+f"(c[0]), "+f"(c[1]), "+f"(c[2]), "+f"(c[3])
        : "r"(a[0]), "r"(a[1]), "r"(a[2]), "r"(a[3]), "r"(b0), "r"(b1));
}
__device__ __forceinline__ void mma_bf16(float c[4], const unsigned a[4], unsigned b0,
                                         unsigned b1) {
    asm volatile(
        "mma.sync.aligned.m16n8k16.row.col.f32.bf16.bf16.f32 "
        "{%0,%1,%2,%3}, {%4,%5,%6,%7}, {%8,%9}, {%0,%1,%2,%3};"
        : "+f"(c[0]), "+f"(c[1]), "+f"(c[2]), "+f"(c[3])
        : "r"(a[0]), "r"(a[1]), "r"(a[2]), "r"(a[3]), "r"(b0), "r"(b1));
}
__device__ __forceinline__ void mma3b(float c[4], const unsigned ah[4], const unsigned al[4],
                                      unsigned bh0, unsigned bh1, unsigned bl0, unsigned bl1) {
    mma_bf16(c, ah, bh0, bh1);
    mma_bf16(c, ah, bl0, bl1);
    mma_bf16(c, al, bh0, bh1);
}
__device__ __forceinline__ void ldsm4(unsigned addr, unsigned& r0, unsigned& r1, unsigned& r2,
                                      unsigned& r3) {
    asm volatile("ldmatrix.sync.aligned.m8n8.x4.shared.b16 {%0,%1,%2,%3}, [%4];"
                 : "=r"(r0), "=r"(r1), "=r"(r2), "=r"(r3)
                 : "r"(addr));
}
__device__ __forceinline__ void pack2b(float x, float y, unsigned& hi, unsigned& lo) {
    __nv_bfloat162 h = __floats2bfloat162_rn(x, y);
    __nv_bfloat162 l = __floats2bfloat162_rn(x - __low2float(h), y - __high2float(h));
    hi = *reinterpret_cast<unsigned*>(&h);
    lo = *reinterpret_cast<unsigned*>(&l);
}
__device__ __forceinline__ void cp16(unsigned dst, const void* src, unsigned nbytes) {
    asm volatile("cp.async.cg.shared.global [%0], [%1], 16, %2;"
                 :: "r"(dst), "l"(src), "r"(nbytes) : "memory");
}
#define CP_COMMIT() asm volatile("cp.async.commit_group;" ::: "memory")
#define CP_WAIT1()  asm volatile("cp.async.wait_group 1;" ::: "memory")

// =====================================================================================
// prepack: transpose W[K][N] -> single fp16 [n*rowMul+rowOff][ldo] (k-contiguous)
// =====================================================================================
__global__ void prepack_kernel(const float* __restrict__ W, __half* __restrict__ H,
                               int K, int N, int ldo, int rowMul, int rowOff) {
    __shared__ float t[32][33];
    int tx = threadIdx.x, ty = threadIdx.y;
    int n0 = blockIdx.x * 32, k0 = blockIdx.y * 32;
#pragma unroll
    for (int j = 0; j < 4; j++) {
        int k = k0 + ty + j * 8, n = n0 + tx;
        if (k < K && n < N) t[ty + j * 8][tx] = W[(size_t)k * N + n];
    }
    __syncthreads();
#pragma unroll
    for (int j = 0; j < 4; j++) {
        int n = n0 + ty + j * 8, k = k0 + tx;
        if (k < K && n < N)
            H[(size_t)(n * rowMul + rowOff) * ldo + k] = __float2half(t[tx][ty + j * 8]);
    }
}

// =====================================================================================
// NT tensor-core GEMM, 2-term FP16 (A split hi/lo, B single), cp.async pipeline.
//   C[M,N] = A[M,K] @ B[N,K]^T.  geglu_mode: interleaved gate/up epilogue -> fp16 hi/lo.
// =====================================================================================
#define GSTAGES 3
#define GEMM_SMEM (GSTAGES * 12288)

__global__ __launch_bounds__(256, 2) void gemm_kernel(
    const __half* __restrict__ Ah, const __half* __restrict__ Al,
    const __half* __restrict__ Bh,
    float* __restrict__ Cf, __half* __restrict__ GoH, __half* __restrict__ GoL,
    int lda, int ldb, int ldc, int M, int N, int K, int geglu_mode) {
    extern __shared__ __align__(16) unsigned short sm[];
    unsigned smBase = smem_u32(sm);
    const int tid = threadIdx.x;
    const int m0 = blockIdx.y * 128, n0 = blockIdx.x * 128;
    const int aRow = tid >> 1, aK = (tid & 1) * 8;
    const int physSt = (aK >> 3) ^ ((aRow >> 2) & 1);
    const unsigned stOff = aRow * 32 + physSt * 16;
    const __half* ApH = Ah + (size_t)(m0 + aRow) * lda + aK;
    const __half* ApL = Al + (size_t)(m0 + aRow) * lda + aK;
    const int gn = n0 + aRow;
    const unsigned bBytes = (gn < N) ? 16u : 0u;
    const int gnc = (gn < N) ? gn : (N - 1);
    const __half* BpH = Bh + (size_t)gnc * ldb + aK;

    const int lane = tid & 31, warp = tid >> 5;
    const int g = lane >> 2, t = lane & 3;
    const int wM = (warp >> 2) * 64, wN = (warp & 3) * 32;
    const int lr = lane & 15, kc = lane >> 4;
    unsigned offA[4], offB[2];
#pragma unroll
    for (int mt = 0; mt < 4; mt++) {
        int r = wM + mt * 16 + lr;
        int ph = kc ^ ((r >> 2) & 1);
        offA[mt] = r * 32 + ph * 16;
    }
#pragma unroll
    for (int p = 0; p < 2; p++) {
        int r = wN + p * 16 + lr;
        int ph = kc ^ ((r >> 2) & 1);
        offB[p] = 8192 + r * 32 + ph * 16;
    }

    float acc[4][4][4];
#pragma unroll
    for (int i = 0; i < 4; i++)
#pragma unroll
        for (int j = 0; j < 4; j++)
#pragma unroll
            for (int r = 0; r < 4; r++) acc[i][j][r] = 0.f;

    const int nT = K >> 4;
    auto LOADA = [&](int stage, int k0) {
        unsigned d = smBase + stage * 12288 + stOff;
        cp16(d, ApH + k0, 16u);
        cp16(d + 4096, ApL + k0, 16u);
        cp16(d + 8192, BpH + k0, bBytes);
        CP_COMMIT();
    };

    LOADA(0, 0);
    if (nT > 1) LOADA(1, 16);
    int stage = 0;
    for (int tt = 0; tt < nT; ++tt) {
        CP_WAIT1();
        __syncthreads();
        if (tt + 2 < nT) {
            int ns = stage + 2;
            if (ns >= GSTAGES) ns -= GSTAGES;
            LOADA(ns, (tt + 2) << 4);
        }
        unsigned bo = smBase + stage * 12288;
        unsigned a_h[4][4], a_l[4][4], b_h[2][4];
#pragma unroll
        for (int mt = 0; mt < 4; mt++) {
            ldsm4(bo + offA[mt], a_h[mt][0], a_h[mt][1], a_h[mt][2], a_h[mt][3]);
            ldsm4(bo + offA[mt] + 4096, a_l[mt][0], a_l[mt][1], a_l[mt][2], a_l[mt][3]);
        }
#pragma unroll
        for (int p = 0; p < 2; p++)
            ldsm4(bo + offB[p], b_h[p][0], b_h[p][1], b_h[p][2], b_h[p][3]);
#pragma unroll
        for (int mt = 0; mt < 4; mt++)
#pragma unroll
            for (int nt = 0; nt < 4; nt++) {
                int p = nt >> 1, od = nt & 1;
                unsigned b0 = b_h[p][od], b1 = b_h[p][od + 2];
                mma_f16(acc[mt][nt], a_h[mt], b0, b1);
                mma_f16(acc[mt][nt], a_l[mt], b0, b1);
            }
        if (++stage == GSTAGES) stage = 0;
    }

    if (geglu_mode) {
#pragma unroll
        for (int mt = 0; mt < 4; mt++) {
            int r = m0 + wM + mt * 16 + g;
#pragma unroll
            for (int nt = 0; nt < 4; nt++) {
                int c = n0 + wN + nt * 8 + 2 * t;    // even; (gate, up) pair
                if (c < N) {
                    int j = c >> 1;
                    float gv0 = acc[mt][nt][0], uv0 = acc[mt][nt][1];
                    float gv1 = acc[mt][nt][2], uv1 = acc[mt][nt][3];
                    float t0 = 0.7978845608028654f * (gv0 + 0.044715f * gv0 * gv0 * gv0);
                    float t1 = 0.7978845608028654f * (gv1 + 0.044715f * gv1 * gv1 * gv1);
                    float o0 = 0.5f * gv0 * (1.f + tanhf(t0)) * uv0;
                    float o1 = 0.5f * gv1 * (1.f + tanhf(t1)) * uv1;
                    splitStoreH(o0, GoH, GoL, (size_t)r * FF_PAD + j);
                    splitStoreH(o1, GoH, GoL, (size_t)(r + 8) * FF_PAD + j);
                }
            }
        }
    } else {
#pragma unroll
        for (int mt = 0; mt < 4; mt++) {
            int r = m0 + wM + mt * 16 + g;
#pragma unroll
            for (int nt = 0; nt < 4; nt++) {
                int c = n0 + wN + nt * 8 + 2 * t;
                if (c < N) {
                    *(float2*)(Cf + (size_t)r * ldc + c) =
                        make_float2(acc[mt][nt][0], acc[mt][nt][1]);
                    *(float2*)(Cf + (size_t)(r + 8) * ldc + c) =
                        make_float2(acc[mt][nt][2], acc[mt][nt][3]);
                }
            }
        }
    }
}

// =====================================================================================
// Flash attention (3xBF16) — per (q-tile 128, bn) block, online softmax.
// Epilogue emits fp16 hi/lo att for the Wo GEMM.
// =====================================================================================
#define SK_OFF 0
#define SKL_OFF 11264
#define SV_OFF 22528
#define SVL_OFF 33408
#define FLASH_SMEM ((22528 + 21760) * 2)

__global__ __launch_bounds__(256, 1) void flash_kernel(
    const bf16* __restrict__ qH, const bf16* __restrict__ qL,
    const bf16* __restrict__ kH, const bf16* __restrict__ kL,
    const bf16* __restrict__ vH, const bf16* __restrict__ vL,
    __half* __restrict__ attH, __half* __restrict__ attL) {
    extern __shared__ __align__(16) unsigned short sm[];
    unsigned short* sKh = sm + SK_OFF;
    unsigned short* sKl = sm + SKL_OFF;
    unsigned short* sVh = sm + SV_OFF;
    unsigned short* sVl = sm + SVL_OFF;
    unsigned smBase = smem_u32(sm);

    const int tid = threadIdx.x;
    const int qt = blockIdx.x, bn = blockIdx.y;
    const int b = bn >> 4, n = bn & 15;
    const int lane = tid & 31, warp = tid >> 5;
    const int g = lane >> 2, t = lane & 3;
    const int lr = lane & 15, kh = lane >> 4;
    const int qRow0 = warp * 16;

    const size_t qkStride = (size_t)NHEADS * HPAD;
    const size_t qBase = ((size_t)(b * L + qt * 128) * NHEADS + n) * HPAD;
    const size_t kBase = ((size_t)(b * L) * NHEADS + n) * HPAD;
    const size_t vBase = ((size_t)bn * HPAD) * L;

#pragma unroll
    for (int i = 0; i < 5; i++) {
        int idx = tid + i * 256;
        int r = idx / 10, c8 = (idx % 10) * 8;
        size_t go = qBase + (size_t)r * qkStride + c8;
        *(uint4*)&sKh[r * 88 + c8] = *(const uint4*)(qH + go);
        *(uint4*)&sKl[r * 88 + c8] = *(const uint4*)(qL + go);
    }
    __syncthreads();
    unsigned qh[5][4], ql[5][4];
#pragma unroll
    for (int ch = 0; ch < 5; ch++) {
        unsigned a = smBase + ((qRow0 + lr) * 88 + ch * 16 + kh * 8) * 2;
        ldsm4(a, qh[ch][0], qh[ch][1], qh[ch][2], qh[ch][3]);
        ldsm4(a + SKL_OFF * 2, ql[ch][0], ql[ch][1], ql[ch][2], ql[ch][3]);
    }
    __syncthreads();

    float Oacc[10][4];
#pragma unroll
    for (int i = 0; i < 10; i++)
#pragma unroll
        for (int j = 0; j < 4; j++) Oacc[i][j] = 0.f;
    float mA = -1e30f, mB = -1e30f, lA = 0.f, lB = 0.f;

    for (int st = 0; st < 8; st++) {
#pragma unroll
        for (int i = 0; i < 5; i++) {
            int idx = tid + i * 256;
            int r = idx / 10, c8 = (idx % 10) * 8;
            size_t go = kBase + (size_t)(st * 128 + r) * qkStride + c8;
            *(uint4*)&sKh[r * 88 + c8] = *(const uint4*)(kH + go);
            *(uint4*)&sKl[r * 88 + c8] = *(const uint4*)(kL + go);
            int vr = idx / 16, vc = (idx % 16) * 8;
            size_t gv = vBase + (size_t)vr * L + st * 128 + vc;
            *(uint4*)&sVh[vr * 136 + vc] = *(const uint4*)(vH + gv);
            *(uint4*)&sVl[vr * 136 + vc] = *(const uint4*)(vL + gv);
        }
        __syncthreads();

        float sacc[16][4];
#pragma unroll
        for (int i = 0; i < 16; i++)
#pragma unroll
            for (int j = 0; j < 4; j++) sacc[i][j] = 0.f;
#pragma unroll
        for (int ch = 0; ch < 5; ch++) {
#pragma unroll
            for (int ng = 0; ng < 8; ng++) {
                unsigned a = smBase + ((ng * 16 + lr) * 88 + ch * 16 + kh * 8) * 2;
                unsigned h0, h1, h2, h3, l0, l1, l2, l3;
                ldsm4(a, h0, h1, h2, h3);
                ldsm4(a + SKL_OFF * 2, l0, l1, l2, l3);
                mma3b(sacc[2 * ng], qh[ch], ql[ch], h0, h2, l0, l2);
                mma3b(sacc[2 * ng + 1], qh[ch], ql[ch], h1, h3, l1, l3);
            }
        }

        float tmA = -1e30f, tmB = -1e30f;
#pragma unroll
        for (int i = 0; i < 16; i++) {
            tmA = fmaxf(tmA, fmaxf(sacc[i][0], sacc[i][1]));
            tmB = fmaxf(tmB, fmaxf(sacc[i][2], sacc[i][3]));
        }
        tmA = fmaxf(tmA, __shfl_xor_sync(0xffffffffu, tmA, 1));
        tmA = fmaxf(tmA, __shfl_xor_sync(0xffffffffu, tmA, 2));
        tmB = fmaxf(tmB, __shfl_xor_sync(0xffffffffu, tmB, 1));
        tmB = fmaxf(tmB, __shfl_xor_sync(0xffffffffu, tmB, 2));
        float mnA = fmaxf(mA, tmA), mnB = fmaxf(mB, tmB);
        float fA = __expf(mA - mnA), fB = __expf(mB - mnB);
        mA = mnA; mB = mnB;
        float sA = 0.f, sB = 0.f;
#pragma unroll
        for (int i = 0; i < 16; i++) {
            sacc[i][0] = __expf(sacc[i][0] - mnA);
            sacc[i][1] = __expf(sacc[i][1] - mnA);
            sacc[i][2] = __expf(sacc[i][2] - mnB);
            sacc[i][3] = __expf(sacc[i][3] - mnB);
            sA += sacc[i][0] + sacc[i][1];
            sB += sacc[i][2] + sacc[i][3];
        }
        sA += __shfl_xor_sync(0xffffffffu, sA, 1);
        sA += __shfl_xor_sync(0xffffffffu, sA, 2);
        sB += __shfl_xor_sync(0xffffffffu, sB, 1);
        sB += __shfl_xor_sync(0xffffffffu, sB, 2);
        lA = lA * fA + sA;
        lB = lB * fB + sB;
#pragma unroll
        for (int i = 0; i < 10; i++) {
            Oacc[i][0] *= fA; Oacc[i][1] *= fA;
            Oacc[i][2] *= fB; Oacc[i][3] *= fB;
        }

#pragma unroll
        for (int kc = 0; kc < 8; kc++) {
            unsigned ah[4], al[4];
            pack2b(sacc[2 * kc][0], sacc[2 * kc][1], ah[0], al[0]);
            pack2b(sacc[2 * kc][2], sacc[2 * kc][3], ah[1], al[1]);
            pack2b(sacc[2 * kc + 1][0], sacc[2 * kc + 1][1], ah[2], al[2]);
            pack2b(sacc[2 * kc + 1][2], sacc[2 * kc + 1][3], ah[3], al[3]);
#pragma unroll
            for (int vg = 0; vg < 5; vg++) {
                unsigned a = smBase + SV_OFF * 2 + ((vg * 16 + lr) * 136 + kc * 16 + kh * 8) * 2;
                unsigned h0, h1, h2, h3, l0, l1, l2, l3;
                ldsm4(a, h0, h1, h2, h3);
                ldsm4(a + (SVL_OFF - SV_OFF) * 2, l0, l1, l2, l3);
                mma3b(Oacc[2 * vg], ah, al, h0, h2, l0, l2);
                mma3b(Oacc[2 * vg + 1], ah, al, h1, h3, l1, l3);
            }
        }
        __syncthreads();
    }

    float invA = 1.f / lA, invB = 1.f / lB;
    int row0 = b * L + qt * 128 + qRow0 + g;
#pragma unroll
    for (int nt = 0; nt < 9; nt++) {
        int c = n * HDIM + nt * 8 + 2 * t;
        size_t i0 = (size_t)row0 * DIM + c;
        size_t i1 = (size_t)(row0 + 8) * DIM + c;
        splitStoreH(Oacc[nt][0] * invA, attH, attL, i0);
        splitStoreH(Oacc[nt][1] * invA, attH, attL, i0 + 1);
        splitStoreH(Oacc[nt][2] * invB, attH, attL, i1);
        splitStoreH(Oacc[nt][3] * invB, attH, attL, i1 + 1);
    }
}

// ---------------- patchify -> fp16 hi/lo ----------------
__global__ void patchify_kernel(const float* __restrict__ img, __half* __restrict__ PH,
                                __half* __restrict__ PL) {
    int idx = blockIdx.x * blockDim.x + threadIdx.x;
    if (idx >= BL * PATCHD) return;
    int bl = idx / PATCHD, j = idx % PATCHD;
    int b = bl >> 10, l = bl & 1023;
    int gy = l >> 5, gx = l & 31;
    int py = j / 48, r = j % 48;
    int px = r / 3, c = r % 3;
    int row = gy * 16 + py, col = gx * 16 + px;
    float v = 2.0f * img[(((size_t)b * 512 + row) * 512 + col) * 3 + c] - 1.0f;
    splitStoreH(v, PH, PL, idx);
}

// ---------------- pos-emb add ----------------
__global__ void add_posemb_kernel(float* __restrict__ x, const float* __restrict__ pe) {
    int idx = blockIdx.x * blockDim.x + threadIdx.x;
    if (idx >= BL * DIM) return;
    int bl = idx / DIM, d = idx % DIM;
    int l = bl & 1023;
    int posx = l & 31, posy = l >> 5;
    x[idx] += pe[(size_t)(posx * 2 + 0) * DIM + d] + pe[(size_t)(posy * 2 + 1) * DIM + d];
}

// ---------------- row RMSNorm -> fp16 hi/lo (entry) ----------------
__global__ void rmsnorm_kernel(const float* __restrict__ in, const float* __restrict__ scale,
                               __half* __restrict__ outH, __half* __restrict__ outL) {
    int row = blockIdx.x;
    const float* p = in + (size_t)row * DIM;
    float s = 0.f;
    for (int i = threadIdx.x; i < DIM; i += 256) { float v = p[i]; s += v * v; }
    __shared__ float red[256];
    red[threadIdx.x] = s; __syncthreads();
    for (int st = 128; st > 0; st >>= 1) {
        if (threadIdx.x < st) red[threadIdx.x] += red[threadIdx.x + st];
        __syncthreads();
    }
    float rs = rsqrtf(red[0] / (float)DIM + EPS);
    for (int i = threadIdx.x; i < DIM; i += 256)
        splitStoreH(p[i] * rs * (1.f + scale[i]), outH, outL, (size_t)row * DIM + i);
}

// ---------------- fused: x += rms(o)*(1+rsc); h = rms(x)*(1+nsc) -> fp16 hi/lo ----------
__global__ void resid_rms_norm_kernel(float* __restrict__ x, const float* __restrict__ o,
                                      const float* __restrict__ rsc,
                                      const float* __restrict__ nsc,
                                      __half* __restrict__ outH, __half* __restrict__ outL) {
    int row = blockIdx.x;
    const float* po = o + (size_t)row * DIM;
    float* px = x + (size_t)row * DIM;
    float ov[5], xv[5];
    float s = 0.f;
#pragma unroll
    for (int j = 0; j < 5; j++) {
        int i = threadIdx.x + j * 256;
        if (i < DIM) { ov[j] = po[i]; xv[j] = px[i]; s += ov[j] * ov[j]; }
        else { ov[j] = 0.f; xv[j] = 0.f; }
    }
    __shared__ float red[256];
    red[threadIdx.x] = s; __syncthreads();
    for (int st = 128; st > 0; st >>= 1) {
        if (threadIdx.x < st) red[threadIdx.x] += red[threadIdx.x + st];
        __syncthreads();
    }
    float rs = rsqrtf(red[0] / (float)DIM + EPS);
    __syncthreads();
    float s2 = 0.f;
#pragma unroll
    for (int j = 0; j < 5; j++) {
        int i = threadIdx.x + j * 256;
        if (i < DIM) {
            xv[j] += ov[j] * rs * (1.f + rsc[i]);
            s2 += xv[j] * xv[j];
            px[i] = xv[j];
        }
    }
    red[threadIdx.x] = s2; __syncthreads();
    for (int st = 128; st > 0; st >>= 1) {
        if (threadIdx.x < st) red[threadIdx.x] += red[threadIdx.x + st];
        __syncthreads();
    }
    float rs2 = rsqrtf(red[0] / (float)DIM + EPS);
#pragma unroll
    for (int j = 0; j < 5; j++) {
        int i = threadIdx.x + j * 256;
        if (i < DIM)
            splitStoreH(xv[j] * rs2 * (1.f + nsc[i]), outH, outL, (size_t)row * DIM + i);
    }
}

// ---------------- fused: x += rms(o)*(1+rsc); out = (x*sqrtD - bias)*scale ----------------
__global__ void resid_final_kernel(const float* __restrict__ x, const float* __restrict__ o,
                                   const float* __restrict__ rsc,
                                   const float* __restrict__ bias,
                                   const float* __restrict__ scl, float* __restrict__ out) {
    int row = blockIdx.x;
    const float* po = o + (size_t)row * DIM;
    const float* px = x + (size_t)row * DIM;
    float ov[5];
    float s = 0.f;
#pragma unroll
    for (int j = 0; j < 5; j++) {
        int i = threadIdx.x + j * 256;
        ov[j] = (i < DIM) ? po[i] : 0.f;
        s += ov[j] * ov[j];
    }
    __shared__ float red[256];
    red[threadIdx.x] = s; __syncthreads();
    for (int st = 128; st > 0; st >>= 1) {
        if (threadIdx.x < st) red[threadIdx.x] += red[threadIdx.x + st];
        __syncthreads();
    }
    float rs = rsqrtf(red[0] / (float)DIM + EPS);
#pragma unroll
    for (int j = 0; j < 5; j++) {
        int i = threadIdx.x + j * 256;
        if (i < DIM) {
            float xn = px[i] + ov[j] * rs * (1.f + rsc[i]);
            out[(size_t)row * DIM + i] = (xn * 33.941125496954285f - bias[i]) * scl[i];
        }
    }
}

// ---------------- fused per-head RMS (+2D RoPE): blockIdx.y = 0:q 1:k 2:v (bf16 out) -----
__global__ void head_finish_fused(const float* __restrict__ qkv,
                                  const float* __restrict__ qn, const float* __restrict__ kn,
                                  const float* __restrict__ vn,
                                  bf16* __restrict__ qpH, bf16* __restrict__ qpL,
                                  bf16* __restrict__ kpH, bf16* __restrict__ kpL,
                                  bf16* __restrict__ vtH, bf16* __restrict__ vtL,
                                  float qk_scale) {
    int sec = blockIdx.y;
    const float* scale = (sec == 0) ? qn : ((sec == 1) ? kn : vn);
    float premul = (sec == 0) ? qk_scale : 1.f;
    int warp = threadIdx.x >> 5, lane = threadIdx.x & 31;
    int item = blockIdx.x * 8 + warp;
    int token = item >> 4;
    int head = item & 15;
    const float* p = qkv + (size_t)token * QKVD + sec * DIM + head * HDIM;
    float v0 = p[lane];
    float v1 = p[lane + 32];
    float v2 = (lane < 8) ? p[lane + 64] : 0.f;
    float s = v0 * v0 + v1 * v1 + v2 * v2;
#pragma unroll
    for (int off = 16; off; off >>= 1) s += __shfl_xor_sync(0xffffffffu, s, off);
    float rs = rsqrtf(s / (float)HDIM + EPS) * premul;
    __shared__ float buf[8][HDIM];
    buf[warp][lane] = v0 * rs * (1.f + scale[lane]);
    buf[warp][lane + 32] = v1 * rs * (1.f + scale[lane + 32]);
    if (lane < 8) buf[warp][lane + 64] = v2 * rs * (1.f + scale[lane + 64]);
    __syncwarp();
    if (sec < 2) {
        int l = token & 1023;
        float posx = (float)(l & 31), posy = (float)(l >> 5);
        for (int pp = lane; pp < 36; pp += 32) {
            int j = (pp < 18) ? pp : (pp - 18);
            float pos = (pp < 18) ? posx : posy;
            int d1 = (pp < 18) ? pp : (pp + 18);
            int d2 = d1 + 18;
            float ts = powf(100.f, (float)j / 18.f);
            float ang = pos / ts;
            float sn, cs;
            sincosf(ang, &sn, &cs);
            float a = buf[warp][d1], b2 = buf[warp][d2];
            buf[warp][d1] = a * cs - b2 * sn;
            buf[warp][d2] = b2 * cs + a * sn;
        }
        __syncwarp();
    }
    if (sec < 2) {
        bf16* oH = (sec == 0) ? qpH : kpH;
        bf16* oL = (sec == 0) ? qpL : kpL;
        size_t base = ((size_t)token * NHEADS + head) * HPAD;
        splitStoreB(buf[warp][lane], oH, oL, base + lane);
        splitStoreB(buf[warp][lane + 32], oH, oL, base + lane + 32);
        if (lane < 8) splitStoreB(buf[warp][lane + 64], oH, oL, base + lane + 64);
    } else {
        int b = token >> 10, l = token & 1023;
        size_t base = ((size_t)(b * NHEADS + head) * HPAD) * L + l;
        splitStoreB(buf[warp][lane], vtH, vtL, base + (size_t)lane * L);
        splitStoreB(buf[warp][lane + 32], vtH, vtL, base + (size_t)(lane + 32) * L);
        if (lane < 8) splitStoreB(buf[warp][lane + 64], vtH, vtL, base + (size_t)(lane + 64) * L);
    }
}

// ---------------- launcher ----------------
extern "C" void kernel_launch(void* const* d_in, const int* in_sizes, int n_in,
                              void* d_out, int out_size) {
    const float* inputs    = (const float*)d_in[0];
    const float* Wp        = (const float*)d_in[1];
    const float* posemb    = (const float*)d_in[2];
    const float* Wq        = (const float*)d_in[3];
    const float* Wk        = (const float*)d_in[4];
    const float* Wv        = (const float*)d_in[5];
    const float* Wo        = (const float*)d_in[6];
    const float* Wg        = (const float*)d_in[7];
    const float* Wu        = (const float*)d_in[8];
    const float* Wd        = (const float*)d_in[9];
    const float* qn        = (const float*)d_in[10];
    const float* kn        = (const float*)d_in[11];
    const float* vn        = (const float*)d_in[12];
    const float* pre_attn  = (const float*)d_in[13];
    const float* post_attn = (const float*)d_in[14];
    const float* pre_ffw   = (const float*)d_in[15];
    const float* post_ffw  = (const float*)d_in[16];
    const float* std_bias  = (const float*)d_in[17];
    const float* std_scale = (const float*)d_in[18];
    float* out = (float*)d_out;

    float *x, *qkv, *o;
    cudaGetSymbolAddress((void**)&x, g_x);
    cudaGetSymbolAddress((void**)&qkv, g_qkv);
    cudaGetSymbolAddress((void**)&o, g_o);
    __half *patH, *patL, *hH, *hL, *attH, *attL, *gH, *gL;
    cudaGetSymbolAddress((void**)&patH, g_patH); cudaGetSymbolAddress((void**)&patL, g_patL);
    cudaGetSymbolAddress((void**)&hH, g_hH);     cudaGetSymbolAddress((void**)&hL, g_hL);
    cudaGetSymbolAddress((void**)&attH, g_attH); cudaGetSymbolAddress((void**)&attL, g_attL);
    cudaGetSymbolAddress((void**)&gH, g_gH);     cudaGetSymbolAddress((void**)&gL, g_gL);
    bf16 *qpH, *qpL, *kpH, *kpL, *vtH, *vtL;
    cudaGetSymbolAddress((void**)&qpH, g_qpH);   cudaGetSymbolAddress((void**)&qpL, g_qpL);
    cudaGetSymbolAddress((void**)&kpH, g_kpH);   cudaGetSymbolAddress((void**)&kpL, g_kpL);
    cudaGetSymbolAddress((void**)&vtH, g_vtH);   cudaGetSymbolAddress((void**)&vtL, g_vtL);
    __half *WpH, *WqkvH, *WoH, *WguH, *WdH;
    cudaGetSymbolAddress((void**)&WpH, g_WpH);
    cudaGetSymbolAddress((void**)&WqkvH, g_WqkvH);
    cudaGetSymbolAddress((void**)&WoH, g_WoH);
    cudaGetSymbolAddress((void**)&WguH, g_WguH);
    cudaGetSymbolAddress((void**)&WdH, g_WdH);

    const float qk_scale = 0.11785113019775793f;  // 1/sqrt(72)
    dim3 tb(32, 8);

    static cudaStream_t s2 = nullptr;
    static cudaEvent_t evFork, evWp, evL[NLAYERS];
    static bool attr_set = false;
    if (!attr_set) {
        cudaFuncSetAttribute(flash_kernel, cudaFuncAttributeMaxDynamicSharedMemorySize,
                             FLASH_SMEM);
        cudaFuncSetAttribute(gemm_kernel, cudaFuncAttributeMaxDynamicSharedMemorySize,
                             GEMM_SMEM);
        cudaStreamCreateWithFlags(&s2, cudaStreamNonBlocking);
        cudaEventCreateWithFlags(&evFork, cudaEventDisableTiming);
        cudaEventCreateWithFlags(&evWp, cudaEventDisableTiming);
        for (int i = 0; i < NLAYERS; i++)
            cudaEventCreateWithFlags(&evL[i], cudaEventDisableTiming);
        attr_set = true;
    }

    // ---- fork prepack stream (single fp16 weights) ----
    cudaEventRecord(evFork, 0);
    cudaStreamWaitEvent(s2, evFork, 0);
    prepack_kernel<<<dim3((DIM + 31) / 32, (PATCHD + 31) / 32), tb, 0, s2>>>(
        Wp, WpH, PATCHD, DIM, PATCHD, 1, 0);
    cudaEventRecord(evWp, s2);
    for (int i = 0; i < NLAYERS; i++) {
        size_t so = (size_t)i * DIM * DIM;
        size_t qo = (size_t)i * QKVD * DIM;
        prepack_kernel<<<dim3(36, 36), tb, 0, s2>>>(Wq + so, WqkvH + qo, DIM, DIM, DIM, 1, 0);
        prepack_kernel<<<dim3(36, 36), tb, 0, s2>>>(Wk + so, WqkvH + qo + (size_t)DIM * DIM,
                                                    DIM, DIM, DIM, 1, 0);
        prepack_kernel<<<dim3(36, 36), tb, 0, s2>>>(Wv + so, WqkvH + qo + 2 * (size_t)DIM * DIM,
                                                    DIM, DIM, DIM, 1, 0);
        prepack_kernel<<<dim3(36, 36), tb, 0, s2>>>(Wo + so, WoH + so, DIM, DIM, DIM, 1, 0);
        size_t fo = (size_t)i * DIM * FF;
        size_t go = (size_t)i * GUD * DIM;
        size_t fp = (size_t)i * DIM * FF_PAD;
        prepack_kernel<<<dim3((FF + 31) / 32, 36), tb, 0, s2>>>(Wg + fo, WguH + go,
                                                                DIM, FF, DIM, 2, 0);
        prepack_kernel<<<dim3((FF + 31) / 32, 36), tb, 0, s2>>>(Wu + fo, WguH + go,
                                                                DIM, FF, DIM, 2, 1);
        prepack_kernel<<<dim3(36, (FF + 31) / 32), tb, 0, s2>>>(Wd + fo, WdH + fp,
                                                                FF, DIM, FF_PAD, 1, 0);
        cudaEventRecord(evL[i], s2);
    }

    // ---- entry ----
    patchify_kernel<<<(BL * PATCHD + 255) / 256, 256>>>(inputs, patH, patL);
    cudaStreamWaitEvent(0, evWp, 0);
    gemm_kernel<<<dim3(9, 16), 256, GEMM_SMEM>>>(patH, patL, WpH, x, nullptr, nullptr,
                                                 PATCHD, PATCHD, DIM, BL, DIM, PATCHD, 0);
    add_posemb_kernel<<<(BL * DIM + 255) / 256, 256>>>(x, posemb);
    rmsnorm_kernel<<<BL, 256>>>(x, pre_attn, hH, hL);

    for (int i = 0; i < NLAYERS; i++) {
        size_t so = (size_t)i * DIM * DIM;
        size_t qo = (size_t)i * QKVD * DIM;
        size_t go = (size_t)i * GUD * DIM;
        size_t fp = (size_t)i * DIM * FF_PAD;

        cudaStreamWaitEvent(0, evL[i], 0);

        // attention
        gemm_kernel<<<dim3(27, 16), 256, GEMM_SMEM>>>(hH, hL, WqkvH + qo, qkv, nullptr,
                                                      nullptr, DIM, DIM, QKVD,
                                                      BL, QKVD, DIM, 0);
        head_finish_fused<<<dim3(BL * NHEADS / 8, 3), 256>>>(qkv, qn + i * HDIM, kn + i * HDIM,
                                                             vn + i * HDIM, qpH, qpL, kpH, kpL,
                                                             vtH, vtL, qk_scale);
        flash_kernel<<<dim3(8, 32), 256, FLASH_SMEM>>>(qpH, qpL, kpH, kpL, vtH, vtL,
                                                       attH, attL);
        gemm_kernel<<<dim3(9, 16), 256, GEMM_SMEM>>>(attH, attL, WoH + so, o, nullptr,
                                                     nullptr, DIM, DIM, DIM, BL, DIM, DIM, 0);
        resid_rms_norm_kernel<<<BL, 256>>>(x, o, post_attn + i * DIM, pre_ffw + i * DIM,
                                           hH, hL);

        // GeGLU MLP: gate/up GEMM with fused geglu epilogue -> gH/gL
        gemm_kernel<<<dim3(68, 16), 256, GEMM_SMEM>>>(hH, hL, WguH + go, nullptr, gH, gL,
                                                      DIM, DIM, 0, BL, GUD, DIM, 1);
        gemm_kernel<<<dim3(9, 16), 256, GEMM_SMEM>>>(gH, gL, WdH + fp, o, nullptr, nullptr,
                                                     FF_PAD, FF_PAD, DIM, BL, DIM, FF_PAD, 0);
        if (i < NLAYERS - 1) {
            resid_rms_norm_kernel<<<BL, 256>>>(x, o, post_ffw + i * DIM,
                                               pre_attn + (i + 1) * DIM, hH, hL);
        } else {
            resid_final_kernel<<<BL, 256>>>(x, o, post_ffw + i * DIM, std_bias, std_scale,
                                            out);
        }
    }
}

// round 13
// speedup vs baseline: 1.3911x; 1.0308x over previous
#include <cuda_runtime.h>
#include <cuda_bf16.h>
#include <cuda_fp16.h>
#include <math.h>

#define BATCH 2
#define L 1024
#define BL 2048
#define DIM 1152
#define QKVD 3456          // 3*DIM
#define NHEADS 16
#define HDIM 72
#define HPAD 80
#define FF 4304
#define FF_PAD 4352
#define GUD 8608           // 2*FF interleaved (gate_j at 2j, up_j at 2j+1)
#define NLAYERS 4
#define PATCHD 768
#define EPS 1e-6f

typedef __nv_bfloat16 bf16;

// ---------------- f32 scratch ----------------
__device__ float g_x[BL * DIM];
__device__ float g_qkv[(size_t)BL * QKVD];
__device__ float g_o[BL * DIM];

// ---------------- fp16 hi/lo activation scratch (GEMM A operands) ----------------
__device__ __half g_patH[BL * PATCHD], g_patL[BL * PATCHD];
__device__ __half g_hH[BL * DIM], g_hL[BL * DIM];
__device__ __half g_attH[BL * DIM], g_attL[BL * DIM];
__device__ __half g_gH[(size_t)BL * FF_PAD], g_gL[(size_t)BL * FF_PAD];

// ---------------- bf16 hi/lo flash operands ----------------
__device__ bf16 g_qpH[BL * NHEADS * HPAD], g_qpL[BL * NHEADS * HPAD];
__device__ bf16 g_kpH[BL * NHEADS * HPAD], g_kpL[BL * NHEADS * HPAD];
__device__ bf16 g_vtH[BATCH * NHEADS * HPAD * L], g_vtL[BATCH * NHEADS * HPAD * L];

// ---------------- single-fp16 transposed weights [N][K] ----------------
__device__ __half g_WpH[DIM * PATCHD];
__device__ __half g_WqkvH[(size_t)NLAYERS * QKVD * DIM];
__device__ __half g_WoH[NLAYERS * DIM * DIM];
__device__ __half g_WguH[(size_t)NLAYERS * GUD * DIM];
__device__ __half g_WdH[(size_t)NLAYERS * DIM * FF_PAD];

__device__ __forceinline__ void splitStoreH(float v, __half* H, __half* Lo, size_t idx) {
    __half h = __float2half(v);
    H[idx] = h;
    Lo[idx] = __float2half(v - __half2float(h));
}
__device__ __forceinline__ void splitStoreB(float v, bf16* H, bf16* Lo, size_t idx) {
    bf16 h = __float2bfloat16(v);
    H[idx] = h;
    Lo[idx] = __float2bfloat16(v - __bfloat162float(h));
}
__device__ __forceinline__ unsigned smem_u32(const void* p) {
    unsigned a;
    asm("{ .reg .u64 t; cvta.to.shared.u64 t, %1; cvt.u32.u64 %0, t; }" : "=r"(a) : "l"(p));
    return a;
}
__device__ __forceinline__ void mma_f16(float c[4], const unsigned a[4], unsigned b0,
                                        unsigned b1) {
    asm volatile(
        "mma.sync.aligned.m16n8k16.row.col.f32.f16.f16.f32 "
        "{%0,%1,%2,%3}, {%4,%5,%6,%7}, {%8,%9}, {%0,%1,%2,%3};"
        : "+f"(c[0]), "+f"(c[1]), "+f"(c[2]), "+f"(c[3])
        : "r"(a[0]), "r"(a[1]), "r"(a[2]), "r"(a[3]), "r"(b0), "r"(b1));
}
__device__ __forceinline__ void mma_bf16(float c[4], const unsigned a[4], unsigned b0,
                                         unsigned b1) {
    asm volatile(
        "mma.sync.aligned.m16n8k16.row.col.f32.bf16.bf16.f32 "
        "{%0,%1,%2,%3}, {%4,%5,%6,%7}, {%8,%9}, {%0,%1,%2,%3};"
        : "+f"(c[0]), "+f"(c[1]), "+f"(c[2]), "+f"(c[3])
        : "r"(a[0]), "r"(a[1]), "r"(a[2]), "r"(a[3]), "r"(b0), "r"(b1));
}
__device__ __forceinline__ void mma3b(float c[4], const unsigned ah[4], const unsigned al[4],
                                      unsigned bh0, unsigned bh1, unsigned bl0, unsigned bl1) {
    mma_bf16(c, ah, bh0, bh1);
    mma_bf16(c, ah, bl0, bl1);
    mma_bf16(c, al, bh0, bh1);
}
__device__ __forceinline__ void ldsm4(unsigned addr, unsigned& r0, unsigned& r1, unsigned& r2,
                                      unsigned& r3) {
    asm volatile("ldmatrix.sync.aligned.m8n8.x4.shared.b16 {%0,%1,%2,%3}, [%4];"
                 : "=r"(r0), "=r"(r1), "=r"(r2), "=r"(r3)
                 : "r"(addr));
}
__device__ __forceinline__ void pack2b(float x, float y, unsigned& hi, unsigned& lo) {
    __nv_bfloat162 h = __floats2bfloat162_rn(x, y);
    __nv_bfloat162 l = __floats2bfloat162_rn(x - __low2float(h), y - __high2float(h));
    hi = *reinterpret_cast<unsigned*>(&h);
    lo = *reinterpret_cast<unsigned*>(&l);
}
__device__ __forceinline__ void cp16(unsigned dst, const void* src, unsigned nbytes) {
    asm volatile("cp.async.cg.shared.global [%0], [%1], 16, %2;"
                 :: "r"(dst), "l"(src), "r"(nbytes) : "memory");
}
#define CP_COMMIT() asm volatile("cp.async.commit_group;" ::: "memory")
#define CP_WAIT1()  asm volatile("cp.async.wait_group 1;" ::: "memory")

// =====================================================================================
// prepack: transpose W[K][N] -> single fp16 [n*rowMul+rowOff][ldo] (k-contiguous)
// =====================================================================================
__global__ void prepack_kernel(const float* __restrict__ W, __half* __restrict__ H,
                               int K, int N, int ldo, int rowMul, int rowOff) {
    __shared__ float t[32][33];
    int tx = threadIdx.x, ty = threadIdx.y;
    int n0 = blockIdx.x * 32, k0 = blockIdx.y * 32;
#pragma unroll
    for (int j = 0; j < 4; j++) {
        int k = k0 + ty + j * 8, n = n0 + tx;
        if (k < K && n < N) t[ty + j * 8][tx] = W[(size_t)k * N + n];
    }
    __syncthreads();
#pragma unroll
    for (int j = 0; j < 4; j++) {
        int n = n0 + ty + j * 8, k = k0 + tx;
        if (k < K && n < N)
            H[(size_t)(n * rowMul + rowOff) * ldo + k] = __float2half(t[tx][ty + j * 8]);
    }
}

// =====================================================================================
// NT tensor-core GEMM, 2-term FP16 (A split hi/lo, B single), cp.async pipeline.
//   C[M,N] = A[M,K] @ B[N,K]^T.
//   gridDim.z = split-K factor; when >1 the epilogue atomically accumulates into Cf
//   (caller must zero Cf first). geglu_mode: interleaved gate/up epilogue (z must be 1).
// =====================================================================================
#define GSTAGES 3
#define GEMM_SMEM (GSTAGES * 12288)

__global__ __launch_bounds__(256, 2) void gemm_kernel(
    const __half* __restrict__ Ah, const __half* __restrict__ Al,
    const __half* __restrict__ Bh,
    float* __restrict__ Cf, __half* __restrict__ GoH, __half* __restrict__ GoL,
    int lda, int ldb, int ldc, int M, int N, int K, int geglu_mode) {
    extern __shared__ __align__(16) unsigned short sm[];
    unsigned smBase = smem_u32(sm);
    const int tid = threadIdx.x;
    const int m0 = blockIdx.y * 128, n0 = blockIdx.x * 128;
    const int kLen = K / gridDim.z;             // multiple of 16 by construction
    const int kStart = blockIdx.z * kLen;
    const int aRow = tid >> 1, aK = (tid & 1) * 8;
    const int physSt = (aK >> 3) ^ ((aRow >> 2) & 1);
    const unsigned stOff = aRow * 32 + physSt * 16;
    const __half* ApH = Ah + (size_t)(m0 + aRow) * lda + kStart + aK;
    const __half* ApL = Al + (size_t)(m0 + aRow) * lda + kStart + aK;
    const int gn = n0 + aRow;
    const unsigned bBytes = (gn < N) ? 16u : 0u;
    const int gnc = (gn < N) ? gn : (N - 1);
    const __half* BpH = Bh + (size_t)gnc * ldb + kStart + aK;

    const int lane = tid & 31, warp = tid >> 5;
    const int g = lane >> 2, t = lane & 3;
    const int wM = (warp >> 2) * 64, wN = (warp & 3) * 32;
    const int lr = lane & 15, kc = lane >> 4;
    unsigned offA[4], offB[2];
#pragma unroll
    for (int mt = 0; mt < 4; mt++) {
        int r = wM + mt * 16 + lr;
        int ph = kc ^ ((r >> 2) & 1);
        offA[mt] = r * 32 + ph * 16;
    }
#pragma unroll
    for (int p = 0; p < 2; p++) {
        int r = wN + p * 16 + lr;
        int ph = kc ^ ((r >> 2) & 1);
        offB[p] = 8192 + r * 32 + ph * 16;
    }

    float acc[4][4][4];
#pragma unroll
    for (int i = 0; i < 4; i++)
#pragma unroll
        for (int j = 0; j < 4; j++)
#pragma unroll
            for (int r = 0; r < 4; r++) acc[i][j][r] = 0.f;

    const int nT = kLen >> 4;
    auto LOADA = [&](int stage, int k0) {
        unsigned d = smBase + stage * 12288 + stOff;
        cp16(d, ApH + k0, 16u);
        cp16(d + 4096, ApL + k0, 16u);
        cp16(d + 8192, BpH + k0, bBytes);
        CP_COMMIT();
    };

    LOADA(0, 0);
    if (nT > 1) LOADA(1, 16);
    int stage = 0;
    for (int tt = 0; tt < nT; ++tt) {
        CP_WAIT1();
        __syncthreads();
        if (tt + 2 < nT) {
            int ns = stage + 2;
            if (ns >= GSTAGES) ns -= GSTAGES;
            LOADA(ns, (tt + 2) << 4);
        }
        unsigned bo = smBase + stage * 12288;
        unsigned a_h[4][4], a_l[4][4], b_h[2][4];
#pragma unroll
        for (int mt = 0; mt < 4; mt++) {
            ldsm4(bo + offA[mt], a_h[mt][0], a_h[mt][1], a_h[mt][2], a_h[mt][3]);
            ldsm4(bo + offA[mt] + 4096, a_l[mt][0], a_l[mt][1], a_l[mt][2], a_l[mt][3]);
        }
#pragma unroll
        for (int p = 0; p < 2; p++)
            ldsm4(bo + offB[p], b_h[p][0], b_h[p][1], b_h[p][2], b_h[p][3]);
#pragma unroll
        for (int mt = 0; mt < 4; mt++)
#pragma unroll
            for (int nt = 0; nt < 4; nt++) {
                int p = nt >> 1, od = nt & 1;
                unsigned b0 = b_h[p][od], b1 = b_h[p][od + 2];
                mma_f16(acc[mt][nt], a_h[mt], b0, b1);
                mma_f16(acc[mt][nt], a_l[mt], b0, b1);
            }
        if (++stage == GSTAGES) stage = 0;
    }

    if (geglu_mode) {
#pragma unroll
        for (int mt = 0; mt < 4; mt++) {
            int r = m0 + wM + mt * 16 + g;
#pragma unroll
            for (int nt = 0; nt < 4; nt++) {
                int c = n0 + wN + nt * 8 + 2 * t;    // even; (gate, up) pair
                if (c < N) {
                    int j = c >> 1;
                    float gv0 = acc[mt][nt][0], uv0 = acc[mt][nt][1];
                    float gv1 = acc[mt][nt][2], uv1 = acc[mt][nt][3];
                    float t0 = 0.7978845608028654f * (gv0 + 0.044715f * gv0 * gv0 * gv0);
                    float t1 = 0.7978845608028654f * (gv1 + 0.044715f * gv1 * gv1 * gv1);
                    float o0 = 0.5f * gv0 * (1.f + tanhf(t0)) * uv0;
                    float o1 = 0.5f * gv1 * (1.f + tanhf(t1)) * uv1;
                    splitStoreH(o0, GoH, GoL, (size_t)r * FF_PAD + j);
                    splitStoreH(o1, GoH, GoL, (size_t)(r + 8) * FF_PAD + j);
                }
            }
        }
    } else if (gridDim.z > 1) {
#pragma unroll
        for (int mt = 0; mt < 4; mt++) {
            int r = m0 + wM + mt * 16 + g;
#pragma unroll
            for (int nt = 0; nt < 4; nt++) {
                int c = n0 + wN + nt * 8 + 2 * t;
                if (c < N) {
                    float* p0 = Cf + (size_t)r * ldc + c;
                    float* p1 = Cf + (size_t)(r + 8) * ldc + c;
                    atomicAdd(p0, acc[mt][nt][0]);
                    atomicAdd(p0 + 1, acc[mt][nt][1]);
                    atomicAdd(p1, acc[mt][nt][2]);
                    atomicAdd(p1 + 1, acc[mt][nt][3]);
                }
            }
        }
    } else {
#pragma unroll
        for (int mt = 0; mt < 4; mt++) {
            int r = m0 + wM + mt * 16 + g;
#pragma unroll
            for (int nt = 0; nt < 4; nt++) {
                int c = n0 + wN + nt * 8 + 2 * t;
                if (c < N) {
                    *(float2*)(Cf + (size_t)r * ldc + c) =
                        make_float2(acc[mt][nt][0], acc[mt][nt][1]);
                    *(float2*)(Cf + (size_t)(r + 8) * ldc + c) =
                        make_float2(acc[mt][nt][2], acc[mt][nt][3]);
                }
            }
        }
    }
}

// =====================================================================================
// Flash attention (3xBF16) — per (q-tile 128, bn) block, online softmax.
// Epilogue emits fp16 hi/lo att for the Wo GEMM.
// =====================================================================================
#define SK_OFF 0
#define SKL_OFF 11264
#define SV_OFF 22528
#define SVL_OFF 33408
#define FLASH_SMEM ((22528 + 21760) * 2)

__global__ __launch_bounds__(256, 1) void flash_kernel(
    const bf16* __restrict__ qH, const bf16* __restrict__ qL,
    const bf16* __restrict__ kH, const bf16* __restrict__ kL,
    const bf16* __restrict__ vH, const bf16* __restrict__ vL,
    __half* __restrict__ attH, __half* __restrict__ attL) {
    extern __shared__ __align__(16) unsigned short sm[];
    unsigned short* sKh = sm + SK_OFF;
    unsigned short* sKl = sm + SKL_OFF;
    unsigned short* sVh = sm + SV_OFF;
    unsigned short* sVl = sm + SVL_OFF;
    unsigned smBase = smem_u32(sm);

    const int tid = threadIdx.x;
    const int qt = blockIdx.x, bn = blockIdx.y;
    const int b = bn >> 4, n = bn & 15;
    const int lane = tid & 31, warp = tid >> 5;
    const int g = lane >> 2, t = lane & 3;
    const int lr = lane & 15, kh = lane >> 4;
    const int qRow0 = warp * 16;

    const size_t qkStride = (size_t)NHEADS * HPAD;
    const size_t qBase = ((size_t)(b * L + qt * 128) * NHEADS + n) * HPAD;
    const size_t kBase = ((size_t)(b * L) * NHEADS + n) * HPAD;
    const size_t vBase = ((size_t)bn * HPAD) * L;

#pragma unroll
    for (int i = 0; i < 5; i++) {
        int idx = tid + i * 256;
        int r = idx / 10, c8 = (idx % 10) * 8;
        size_t go = qBase + (size_t)r * qkStride + c8;
        *(uint4*)&sKh[r * 88 + c8] = *(const uint4*)(qH + go);
        *(uint4*)&sKl[r * 88 + c8] = *(const uint4*)(qL + go);
    }
    __syncthreads();
    unsigned qh[5][4], ql[5][4];
#pragma unroll
    for (int ch = 0; ch < 5; ch++) {
        unsigned a = smBase + ((qRow0 + lr) * 88 + ch * 16 + kh * 8) * 2;
        ldsm4(a, qh[ch][0], qh[ch][1], qh[ch][2], qh[ch][3]);
        ldsm4(a + SKL_OFF * 2, ql[ch][0], ql[ch][1], ql[ch][2], ql[ch][3]);
    }
    __syncthreads();

    float Oacc[10][4];
#pragma unroll
    for (int i = 0; i < 10; i++)
#pragma unroll
        for (int j = 0; j < 4; j++) Oacc[i][j] = 0.f;
    float mA = -1e30f, mB = -1e30f, lA = 0.f, lB = 0.f;

    for (int st = 0; st < 8; st++) {
#pragma unroll
        for (int i = 0; i < 5; i++) {
            int idx = tid + i * 256;
            int r = idx / 10, c8 = (idx % 10) * 8;
            size_t go = kBase + (size_t)(st * 128 + r) * qkStride + c8;
            *(uint4*)&sKh[r * 88 + c8] = *(const uint4*)(kH + go);
            *(uint4*)&sKl[r * 88 + c8] = *(const uint4*)(kL + go);
            int vr = idx / 16, vc = (idx % 16) * 8;
            size_t gv = vBase + (size_t)vr * L + st * 128 + vc;
            *(uint4*)&sVh[vr * 136 + vc] = *(const uint4*)(vH + gv);
            *(uint4*)&sVl[vr * 136 + vc] = *(const uint4*)(vL + gv);
        }
        __syncthreads();

        float sacc[16][4];
#pragma unroll
        for (int i = 0; i < 16; i++)
#pragma unroll
            for (int j = 0; j < 4; j++) sacc[i][j] = 0.f;
#pragma unroll
        for (int ch = 0; ch < 5; ch++) {
#pragma unroll
            for (int ng = 0; ng < 8; ng++) {
                unsigned a = smBase + ((ng * 16 + lr) * 88 + ch * 16 + kh * 8) * 2;
                unsigned h0, h1, h2, h3, l0, l1, l2, l3;
                ldsm4(a, h0, h1, h2, h3);
                ldsm4(a + SKL_OFF * 2, l0, l1, l2, l3);
                mma3b(sacc[2 * ng], qh[ch], ql[ch], h0, h2, l0, l2);
                mma3b(sacc[2 * ng + 1], qh[ch], ql[ch], h1, h3, l1, l3);
            }
        }

        float tmA = -1e30f, tmB = -1e30f;
#pragma unroll
        for (int i = 0; i < 16; i++) {
            tmA = fmaxf(tmA, fmaxf(sacc[i][0], sacc[i][1]));
            tmB = fmaxf(tmB, fmaxf(sacc[i][2], sacc[i][3]));
        }
        tmA = fmaxf(tmA, __shfl_xor_sync(0xffffffffu, tmA, 1));
        tmA = fmaxf(tmA, __shfl_xor_sync(0xffffffffu, tmA, 2));
        tmB = fmaxf(tmB, __shfl_xor_sync(0xffffffffu, tmB, 1));
        tmB = fmaxf(tmB, __shfl_xor_sync(0xffffffffu, tmB, 2));
        float mnA = fmaxf(mA, tmA), mnB = fmaxf(mB, tmB);
        float fA = __expf(mA - mnA), fB = __expf(mB - mnB);
        mA = mnA; mB = mnB;
        float sA = 0.f, sB = 0.f;
#pragma unroll
        for (int i = 0; i < 16; i++) {
            sacc[i][0] = __expf(sacc[i][0] - mnA);
            sacc[i][1] = __expf(sacc[i][1] - mnA);
            sacc[i][2] = __expf(sacc[i][2] - mnB);
            sacc[i][3] = __expf(sacc[i][3] - mnB);
            sA += sacc[i][0] + sacc[i][1];
            sB += sacc[i][2] + sacc[i][3];
        }
        sA += __shfl_xor_sync(0xffffffffu, sA, 1);
        sA += __shfl_xor_sync(0xffffffffu, sA, 2);
        sB += __shfl_xor_sync(0xffffffffu, sB, 1);
        sB += __shfl_xor_sync(0xffffffffu, sB, 2);
        lA = lA * fA + sA;
        lB = lB * fB + sB;
#pragma unroll
        for (int i = 0; i < 10; i++) {
            Oacc[i][0] *= fA; Oacc[i][1] *= fA;
            Oacc[i][2] *= fB; Oacc[i][3] *= fB;
        }

#pragma unroll
        for (int kc = 0; kc < 8; kc++) {
            unsigned ah[4], al[4];
            pack2b(sacc[2 * kc][0], sacc[2 * kc][1], ah[0], al[0]);
            pack2b(sacc[2 * kc][2], sacc[2 * kc][3], ah[1], al[1]);
            pack2b(sacc[2 * kc + 1][0], sacc[2 * kc + 1][1], ah[2], al[2]);
            pack2b(sacc[2 * kc + 1][2], sacc[2 * kc + 1][3], ah[3], al[3]);
#pragma unroll
            for (int vg = 0; vg < 5; vg++) {
                unsigned a = smBase + SV_OFF * 2 + ((vg * 16 + lr) * 136 + kc * 16 + kh * 8) * 2;
                unsigned h0, h1, h2, h3, l0, l1, l2, l3;
                ldsm4(a, h0, h1, h2, h3);
                ldsm4(a + (SVL_OFF - SV_OFF) * 2, l0, l1, l2, l3);
                mma3b(Oacc[2 * vg], ah, al, h0, h2, l0, l2);
                mma3b(Oacc[2 * vg + 1], ah, al, h1, h3, l1, l3);
            }
        }
        __syncthreads();
    }

    float invA = 1.f / lA, invB = 1.f / lB;
    int row0 = b * L + qt * 128 + qRow0 + g;
#pragma unroll
    for (int nt = 0; nt < 9; nt++) {
        int c = n * HDIM + nt * 8 + 2 * t;
        size_t i0 = (size_t)row0 * DIM + c;
        size_t i1 = (size_t)(row0 + 8) * DIM + c;
        splitStoreH(Oacc[nt][0] * invA, attH, attL, i0);
        splitStoreH(Oacc[nt][1] * invA, attH, attL, i0 + 1);
        splitStoreH(Oacc[nt][2] * invB, attH, attL, i1);
        splitStoreH(Oacc[nt][3] * invB, attH, attL, i1 + 1);
    }
}

// ---------------- patchify -> fp16 hi/lo ----------------
__global__ void patchify_kernel(const float* __restrict__ img, __half* __restrict__ PH,
                                __half* __restrict__ PL) {
    int idx = blockIdx.x * blockDim.x + threadIdx.x;
    if (idx >= BL * PATCHD) return;
    int bl = idx / PATCHD, j = idx % PATCHD;
    int b = bl >> 10, l = bl & 1023;
    int gy = l >> 5, gx = l & 31;
    int py = j / 48, r = j % 48;
    int px = r / 3, c = r % 3;
    int row = gy * 16 + py, col = gx * 16 + px;
    float v = 2.0f * img[(((size_t)b * 512 + row) * 512 + col) * 3 + c] - 1.0f;
    splitStoreH(v, PH, PL, idx);
}

// ---------------- pos-emb add ----------------
__global__ void add_posemb_kernel(float* __restrict__ x, const float* __restrict__ pe) {
    int idx = blockIdx.x * blockDim.x + threadIdx.x;
    if (idx >= BL * DIM) return;
    int bl = idx / DIM, d = idx % DIM;
    int l = bl & 1023;
    int posx = l & 31, posy = l >> 5;
    x[idx] += pe[(size_t)(posx * 2 + 0) * DIM + d] + pe[(size_t)(posy * 2 + 1) * DIM + d];
}

// ---------------- row RMSNorm -> fp16 hi/lo (entry) ----------------
__global__ void rmsnorm_kernel(const float* __restrict__ in, const float* __restrict__ scale,
                               __half* __restrict__ outH, __half* __restrict__ outL) {
    int row = blockIdx.x;
    const float* p = in + (size_t)row * DIM;
    float s = 0.f;
    for (int i = threadIdx.x; i < DIM; i += 256) { float v = p[i]; s += v * v; }
    __shared__ float red[256];
    red[threadIdx.x] = s; __syncthreads();
    for (int st = 128; st > 0; st >>= 1) {
        if (threadIdx.x < st) red[threadIdx.x] += red[threadIdx.x + st];
        __syncthreads();
    }
    float rs = rsqrtf(red[0] / (float)DIM + EPS);
    for (int i = threadIdx.x; i < DIM; i += 256)
        splitStoreH(p[i] * rs * (1.f + scale[i]), outH, outL, (size_t)row * DIM + i);
}

// ---------------- fused: x += rms(o)*(1+rsc); h = rms(x)*(1+nsc) -> fp16 hi/lo ----------
__global__ void resid_rms_norm_kernel(float* __restrict__ x, const float* __restrict__ o,
                                      const float* __restrict__ rsc,
                                      const float* __restrict__ nsc,
                                      __half* __restrict__ outH, __half* __restrict__ outL) {
    int row = blockIdx.x;
    const float* po = o + (size_t)row * DIM;
    float* px = x + (size_t)row * DIM;
    float ov[5], xv[5];
    float s = 0.f;
#pragma unroll
    for (int j = 0; j < 5; j++) {
        int i = threadIdx.x + j * 256;
        if (i < DIM) { ov[j] = po[i]; xv[j] = px[i]; s += ov[j] * ov[j]; }
        else { ov[j] = 0.f; xv[j] = 0.f; }
    }
    __shared__ float red[256];
    red[threadIdx.x] = s; __syncthreads();
    for (int st = 128; st > 0; st >>= 1) {
        if (threadIdx.x < st) red[threadIdx.x] += red[threadIdx.x + st];
        __syncthreads();
    }
    float rs = rsqrtf(red[0] / (float)DIM + EPS);
    __syncthreads();
    float s2 = 0.f;
#pragma unroll
    for (int j = 0; j < 5; j++) {
        int i = threadIdx.x + j * 256;
        if (i < DIM) {
            xv[j] += ov[j] * rs * (1.f + rsc[i]);
            s2 += xv[j] * xv[j];
            px[i] = xv[j];
        }
    }
    red[threadIdx.x] = s2; __syncthreads();
    for (int st = 128; st > 0; st >>= 1) {
        if (threadIdx.x < st) red[threadIdx.x] += red[threadIdx.x + st];
        __syncthreads();
    }
    float rs2 = rsqrtf(red[0] / (float)DIM + EPS);
#pragma unroll
    for (int j = 0; j < 5; j++) {
        int i = threadIdx.x + j * 256;
        if (i < DIM)
            splitStoreH(xv[j] * rs2 * (1.f + nsc[i]), outH, outL, (size_t)row * DIM + i);
    }
}

// ---------------- fused: x += rms(o)*(1+rsc); out = (x*sqrtD - bias)*scale ----------------
__global__ void resid_final_kernel(const float* __restrict__ x, const float* __restrict__ o,
                                   const float* __restrict__ rsc,
                                   const float* __restrict__ bias,
                                   const float* __restrict__ scl, float* __restrict__ out) {
    int row = blockIdx.x;
    const float* po = o + (size_t)row * DIM;
    const float* px = x + (size_t)row * DIM;
    float ov[5];
    float s = 0.f;
#pragma unroll
    for (int j = 0; j < 5; j++) {
        int i = threadIdx.x + j * 256;
        ov[j] = (i < DIM) ? po[i] : 0.f;
        s += ov[j] * ov[j];
    }
    __shared__ float red[256];
    red[threadIdx.x] = s; __syncthreads();
    for (int st = 128; st > 0; st >>= 1) {
        if (threadIdx.x < st) red[threadIdx.x] += red[threadIdx.x + st];
        __syncthreads();
    }
    float rs = rsqrtf(red[0] / (float)DIM + EPS);
#pragma unroll
    for (int j = 0; j < 5; j++) {
        int i = threadIdx.x + j * 256;
        if (i < DIM) {
            float xn = px[i] + ov[j] * rs * (1.f + rsc[i]);
            out[(size_t)row * DIM + i] = (xn * 33.941125496954285f - bias[i]) * scl[i];
        }
    }
}

// ---------------- fused per-head RMS (+2D RoPE): blockIdx.y = 0:q 1:k 2:v (bf16 out) -----
__global__ void head_finish_fused(const float* __restrict__ qkv,
                                  const float* __restrict__ qn, const float* __restrict__ kn,
                                  const float* __restrict__ vn,
                                  bf16* __restrict__ qpH, bf16* __restrict__ qpL,
                                  bf16* __restrict__ kpH, bf16* __restrict__ kpL,
                                  bf16* __restrict__ vtH, bf16* __restrict__ vtL,
                                  float qk_scale) {
    int sec = blockIdx.y;
    const float* scale = (sec == 0) ? qn : ((sec == 1) ? kn : vn);
    float premul = (sec == 0) ? qk_scale : 1.f;
    int warp = threadIdx.x >> 5, lane = threadIdx.x & 31;
    int item = blockIdx.x * 8 + warp;
    int token = item >> 4;
    int head = item & 15;
    const float* p = qkv + (size_t)token * QKVD + sec * DIM + head * HDIM;
    float v0 = p[lane];
    float v1 = p[lane + 32];
    float v2 = (lane < 8) ? p[lane + 64] : 0.f;
    float s = v0 * v0 + v1 * v1 + v2 * v2;
#pragma unroll
    for (int off = 16; off; off >>= 1) s += __shfl_xor_sync(0xffffffffu, s, off);
    float rs = rsqrtf(s / (float)HDIM + EPS) * premul;
    __shared__ float buf[8][HDIM];
    buf[warp][lane] = v0 * rs * (1.f + scale[lane]);
    buf[warp][lane + 32] = v1 * rs * (1.f + scale[lane + 32]);
    if (lane < 8) buf[warp][lane + 64] = v2 * rs * (1.f + scale[lane + 64]);
    __syncwarp();
    if (sec < 2) {
        int l = token & 1023;
        float posx = (float)(l & 31), posy = (float)(l >> 5);
        for (int pp = lane; pp < 36; pp += 32) {
            int j = (pp < 18) ? pp : (pp - 18);
            float pos = (pp < 18) ? posx : posy;
            int d1 = (pp < 18) ? pp : (pp + 18);
            int d2 = d1 + 18;
            float ts = powf(100.f, (float)j / 18.f);
            float ang = pos / ts;
            float sn, cs;
            sincosf(ang, &sn, &cs);
            float a = buf[warp][d1], b2 = buf[warp][d2];
            buf[warp][d1] = a * cs - b2 * sn;
            buf[warp][d2] = b2 * cs + a * sn;
        }
        __syncwarp();
    }
    if (sec < 2) {
        bf16* oH = (sec == 0) ? qpH : kpH;
        bf16* oL = (sec == 0) ? qpL : kpL;
        size_t base = ((size_t)token * NHEADS + head) * HPAD;
        splitStoreB(buf[warp][lane], oH, oL, base + lane);
        splitStoreB(buf[warp][lane + 32], oH, oL, base + lane + 32);
        if (lane < 8) splitStoreB(buf[warp][lane + 64], oH, oL, base + lane + 64);
    } else {
        int b = token >> 10, l = token & 1023;
        size_t base = ((size_t)(b * NHEADS + head) * HPAD) * L + l;
        splitStoreB(buf[warp][lane], vtH, vtL, base + (size_t)lane * L);
        splitStoreB(buf[warp][lane + 32], vtH, vtL, base + (size_t)(lane + 32) * L);
        if (lane < 8) splitStoreB(buf[warp][lane + 64], vtH, vtL, base + (size_t)(lane + 64) * L);
    }
}

// ---------------- launcher ----------------
extern "C" void kernel_launch(void* const* d_in, const int* in_sizes, int n_in,
                              void* d_out, int out_size) {
    const float* inputs    = (const float*)d_in[0];
    const float* Wp        = (const float*)d_in[1];
    const float* posemb    = (const float*)d_in[2];
    const float* Wq        = (const float*)d_in[3];
    const float* Wk        = (const float*)d_in[4];
    const float* Wv        = (const float*)d_in[5];
    const float* Wo        = (const float*)d_in[6];
    const float* Wg        = (const float*)d_in[7];
    const float* Wu        = (const float*)d_in[8];
    const float* Wd        = (const float*)d_in[9];
    const float* qn        = (const float*)d_in[10];
    const float* kn        = (const float*)d_in[11];
    const float* vn        = (const float*)d_in[12];
    const float* pre_attn  = (const float*)d_in[13];
    const float* post_attn = (const float*)d_in[14];
    const float* pre_ffw   = (const float*)d_in[15];
    const float* post_ffw  = (const float*)d_in[16];
    const float* std_bias  = (const float*)d_in[17];
    const float* std_scale = (const float*)d_in[18];
    float* out = (float*)d_out;

    float *x, *qkv, *o;
    cudaGetSymbolAddress((void**)&x, g_x);
    cudaGetSymbolAddress((void**)&qkv, g_qkv);
    cudaGetSymbolAddress((void**)&o, g_o);
    __half *patH, *patL, *hH, *hL, *attH, *attL, *gH, *gL;
    cudaGetSymbolAddress((void**)&patH, g_patH); cudaGetSymbolAddress((void**)&patL, g_patL);
    cudaGetSymbolAddress((void**)&hH, g_hH);     cudaGetSymbolAddress((void**)&hL, g_hL);
    cudaGetSymbolAddress((void**)&attH, g_attH); cudaGetSymbolAddress((void**)&attL, g_attL);
    cudaGetSymbolAddress((void**)&gH, g_gH);     cudaGetSymbolAddress((void**)&gL, g_gL);
    bf16 *qpH, *qpL, *kpH, *kpL, *vtH, *vtL;
    cudaGetSymbolAddress((void**)&qpH, g_qpH);   cudaGetSymbolAddress((void**)&qpL, g_qpL);
    cudaGetSymbolAddress((void**)&kpH, g_kpH);   cudaGetSymbolAddress((void**)&kpL, g_kpL);
    cudaGetSymbolAddress((void**)&vtH, g_vtH);   cudaGetSymbolAddress((void**)&vtL, g_vtL);
    __half *WpH, *WqkvH, *WoH, *WguH, *WdH;
    cudaGetSymbolAddress((void**)&WpH, g_WpH);
    cudaGetSymbolAddress((void**)&WqkvH, g_WqkvH);
    cudaGetSymbolAddress((void**)&WoH, g_WoH);
    cudaGetSymbolAddress((void**)&WguH, g_WguH);
    cudaGetSymbolAddress((void**)&WdH, g_WdH);

    const float qk_scale = 0.11785113019775793f;  // 1/sqrt(72)
    dim3 tb(32, 8);

    static cudaStream_t s2 = nullptr;
    static cudaEvent_t evFork, evWp, evL[NLAYERS];
    static bool attr_set = false;
    if (!attr_set) {
        cudaFuncSetAttribute(flash_kernel, cudaFuncAttributeMaxDynamicSharedMemorySize,
                             FLASH_SMEM);
        cudaFuncSetAttribute(gemm_kernel, cudaFuncAttributeMaxDynamicSharedMemorySize,
                             GEMM_SMEM);
        cudaStreamCreateWithFlags(&s2, cudaStreamNonBlocking);
        cudaEventCreateWithFlags(&evFork, cudaEventDisableTiming);
        cudaEventCreateWithFlags(&evWp, cudaEventDisableTiming);
        for (int i = 0; i < NLAYERS; i++)
            cudaEventCreateWithFlags(&evL[i], cudaEventDisableTiming);
        attr_set = true;
    }

    // ---- fork prepack stream (single fp16 weights) ----
    cudaEventRecord(evFork, 0);
    cudaStreamWaitEvent(s2, evFork, 0);
    prepack_kernel<<<dim3((DIM + 31) / 32, (PATCHD + 31) / 32), tb, 0, s2>>>(
        Wp, WpH, PATCHD, DIM, PATCHD, 1, 0);
    cudaEventRecord(evWp, s2);
    for (int i = 0; i < NLAYERS; i++) {
        size_t so = (size_t)i * DIM * DIM;
        size_t qo = (size_t)i * QKVD * DIM;
        prepack_kernel<<<dim3(36, 36), tb, 0, s2>>>(Wq + so, WqkvH + qo, DIM, DIM, DIM, 1, 0);
        prepack_kernel<<<dim3(36, 36), tb, 0, s2>>>(Wk + so, WqkvH + qo + (size_t)DIM * DIM,
                                                    DIM, DIM, DIM, 1, 0);
        prepack_kernel<<<dim3(36, 36), tb, 0, s2>>>(Wv + so, WqkvH + qo + 2 * (size_t)DIM * DIM,
                                                    DIM, DIM, DIM, 1, 0);
        prepack_kernel<<<dim3(36, 36), tb, 0, s2>>>(Wo + so, WoH + so, DIM, DIM, DIM, 1, 0);
        size_t fo = (size_t)i * DIM * FF;
        size_t go = (size_t)i * GUD * DIM;
        size_t fp = (size_t)i * DIM * FF_PAD;
        prepack_kernel<<<dim3((FF + 31) / 32, 36), tb, 0, s2>>>(Wg + fo, WguH + go,
                                                                DIM, FF, DIM, 2, 0);
        prepack_kernel<<<dim3((FF + 31) / 32, 36), tb, 0, s2>>>(Wu + fo, WguH + go,
                                                                DIM, FF, DIM, 2, 1);
        prepack_kernel<<<dim3(36, (FF + 31) / 32), tb, 0, s2>>>(Wd + fo, WdH + fp,
                                                                FF, DIM, FF_PAD, 1, 0);
        cudaEventRecord(evL[i], s2);
    }

    // ---- entry ----
    patchify_kernel<<<(BL * PATCHD + 255) / 256, 256>>>(inputs, patH, patL);
    cudaStreamWaitEvent(0, evWp, 0);
    cudaMemsetAsync(x, 0, (size_t)BL * DIM * sizeof(float), 0);
    gemm_kernel<<<dim3(9, 16, 2), 256, GEMM_SMEM>>>(patH, patL, WpH, x, nullptr, nullptr,
                                                    PATCHD, PATCHD, DIM, BL, DIM, PATCHD, 0);
    add_posemb_kernel<<<(BL * DIM + 255) / 256, 256>>>(x, posemb);
    rmsnorm_kernel<<<BL, 256>>>(x, pre_attn, hH, hL);

    for (int i = 0; i < NLAYERS; i++) {
        size_t so = (size_t)i * DIM * DIM;
        size_t qo = (size_t)i * QKVD * DIM;
        size_t go = (size_t)i * GUD * DIM;
        size_t fp = (size_t)i * DIM * FF_PAD;

        cudaStreamWaitEvent(0, evL[i], 0);

        // attention
        cudaMemsetAsync(qkv, 0, (size_t)BL * QKVD * sizeof(float), 0);
        gemm_kernel<<<dim3(27, 16, 2), 256, GEMM_SMEM>>>(hH, hL, WqkvH + qo, qkv, nullptr,
                                                         nullptr, DIM, DIM, QKVD,
                                                         BL, QKVD, DIM, 0);
        head_finish_fused<<<dim3(BL * NHEADS / 8, 3), 256>>>(qkv, qn + i * HDIM, kn + i * HDIM,
                                                             vn + i * HDIM, qpH, qpL, kpH, kpL,
                                                             vtH, vtL, qk_scale);
        flash_kernel<<<dim3(8, 32), 256, FLASH_SMEM>>>(qpH, qpL, kpH, kpL, vtH, vtL,
                                                       attH, attL);
        cudaMemsetAsync(o, 0, (size_t)BL * DIM * sizeof(float), 0);
        gemm_kernel<<<dim3(9, 16, 2), 256, GEMM_SMEM>>>(attH, attL, WoH + so, o, nullptr,
                                                        nullptr, DIM, DIM, DIM,
                                                        BL, DIM, DIM, 0);
        resid_rms_norm_kernel<<<BL, 256>>>(x, o, post_attn + i * DIM, pre_ffw + i * DIM,
                                           hH, hL);

        // GeGLU MLP: gate/up GEMM with fused geglu epilogue -> gH/gL
        gemm_kernel<<<dim3(68, 16, 1), 256, GEMM_SMEM>>>(hH, hL, WguH + go, nullptr, gH, gL,
                                                         DIM, DIM, 0, BL, GUD, DIM, 1);
        cudaMemsetAsync(o, 0, (size_t)BL * DIM * sizeof(float), 0);
        gemm_kernel<<<dim3(9, 16, 2), 256, GEMM_SMEM>>>(gH, gL, WdH + fp, o, nullptr, nullptr,
                                                        FF_PAD, FF_PAD, DIM,
                                                        BL, DIM, FF_PAD, 0);
        if (i < NLAYERS - 1) {
            resid_rms_norm_kernel<<<BL, 256>>>(x, o, post_ffw + i * DIM,
                                               pre_attn + (i + 1) * DIM, hH, hL);
        } else {
            resid_final_kernel<<<BL, 256>>>(x, o, post_ffw + i * DIM, std_bias, std_scale,
                                            out);
        }
    }
}

// round 14
// speedup vs baseline: 1.4152x; 1.0173x over previous
#include <cuda_runtime.h>
#include <cuda_bf16.h>
#include <cuda_fp16.h>
#include <math.h>

#define BATCH 2
#define L 1024
#define BL 2048
#define DIM 1152
#define QKVD 3456          // 3*DIM
#define NHEADS 16
#define HDIM 72
#define HPAD 80
#define FF 4304
#define FF_PAD 4352
#define GUD 8608           // 2*FF interleaved (gate_j at 2j, up_j at 2j+1)
#define NLAYERS 4
#define PATCHD 768
#define EPS 1e-6f

typedef __nv_bfloat16 bf16;

// ---------------- f32 scratch ----------------
__device__ float g_x[BL * DIM];
__device__ float g_op[2 * BL * DIM];                 // split-K partials (patch/Wo/Wd)
__device__ float g_qkvp[(size_t)2 * BL * QKVD];      // split-K partials (QKV)

// ---------------- fp16 hi/lo activation scratch (GEMM A operands) ----------------
__device__ __half g_patH[BL * PATCHD], g_patL[BL * PATCHD];
__device__ __half g_hH[BL * DIM], g_hL[BL * DIM];
__device__ __half g_attH[BL * DIM], g_attL[BL * DIM];
__device__ __half g_gH[(size_t)BL * FF_PAD], g_gL[(size_t)BL * FF_PAD];

// ---------------- bf16 hi/lo flash operands ----------------
__device__ bf16 g_qpH[BL * NHEADS * HPAD], g_qpL[BL * NHEADS * HPAD];
__device__ bf16 g_kpH[BL * NHEADS * HPAD], g_kpL[BL * NHEADS * HPAD];
__device__ bf16 g_vtH[BATCH * NHEADS * HPAD * L], g_vtL[BATCH * NHEADS * HPAD * L];

// ---------------- single-fp16 transposed weights [N][K] ----------------
__device__ __half g_WpH[DIM * PATCHD];
__device__ __half g_WqkvH[(size_t)NLAYERS * QKVD * DIM];
__device__ __half g_WoH[NLAYERS * DIM * DIM];
__device__ __half g_WguH[(size_t)NLAYERS * GUD * DIM];
__device__ __half g_WdH[(size_t)NLAYERS * DIM * FF_PAD];

__device__ __forceinline__ void splitStoreH(float v, __half* H, __half* Lo, size_t idx) {
    __half h = __float2half(v);
    H[idx] = h;
    Lo[idx] = __float2half(v - __half2float(h));
}
__device__ __forceinline__ void splitStoreB(float v, bf16* H, bf16* Lo, size_t idx) {
    bf16 h = __float2bfloat16(v);
    H[idx] = h;
    Lo[idx] = __float2bfloat16(v - __bfloat162float(h));
}
__device__ __forceinline__ unsigned smem_u32(const void* p) {
    unsigned a;
    asm("{ .reg .u64 t; cvta.to.shared.u64 t, %1; cvt.u32.u64 %0, t; }" : "=r"(a) : "l"(p));
    return a;
}
__device__ __forceinline__ void mma_f16(float c[4], const unsigned a[4], unsigned b0,
                                        unsigned b1) {
    asm volatile(
        "mma.sync.aligned.m16n8k16.row.col.f32.f16.f16.f32 "
        "{%0,%1,%2,%3}, {%4,%5,%6,%7}, {%8,%9}, {%0,%1,%2,%3};"
        : "+f"(c[0]), "+f"(c[1]), "+f"(c[2]), "+f"(c[3])
        : "r"(a[0]), "r"(a[1]), "r"(a[2]), "r"(a[3]), "r"(b0), "r"(b1));
}
__device__ __forceinline__ void mma_bf16(float c[4], const unsigned a[4], unsigned b0,
                                         unsigned b1) {
    asm volatile(
        "mma.sync.aligned.m16n8k16.row.col.f32.bf16.bf16.f32 "
        "{%0,%1,%2,%3}, {%4,%5,%6,%7}, {%8,%9}, {%0,%1,%2,%3};"
        : "+f"(c[0]), "+f"(c[1]), "+f"(c[2]), "+f"(c[3])
        : "r"(a[0]), "r"(a[1]), "r"(a[2]), "r"(a[3]), "r"(b0), "r"(b1));
}
__device__ __forceinline__ void mma3b(float c[4], const unsigned ah[4], const unsigned al[4],
                                      unsigned bh0, unsigned bh1, unsigned bl0, unsigned bl1) {
    mma_bf16(c, ah, bh0, bh1);
    mma_bf16(c, ah, bl0, bl1);
    mma_bf16(c, al, bh0, bh1);
}
__device__ __forceinline__ void ldsm4(unsigned addr, unsigned& r0, unsigned& r1, unsigned& r2,
                                      unsigned& r3) {
    asm volatile("ldmatrix.sync.aligned.m8n8.x4.shared.b16 {%0,%1,%2,%3}, [%4];"
                 : "=r"(r0), "=r"(r1), "=r"(r2), "=r"(r3)
                 : "r"(addr));
}
__device__ __forceinline__ void pack2b(float x, float y, unsigned& hi, unsigned& lo) {
    __nv_bfloat162 h = __floats2bfloat162_rn(x, y);
    __nv_bfloat162 l = __floats2bfloat162_rn(x - __low2float(h), y - __high2float(h));
    hi = *reinterpret_cast<unsigned*>(&h);
    lo = *reinterpret_cast<unsigned*>(&l);
}
__device__ __forceinline__ void cp16(unsigned dst, const void* src, unsigned nbytes) {
    asm volatile("cp.async.cg.shared.global [%0], [%1], 16, %2;"
                 :: "r"(dst), "l"(src), "r"(nbytes) : "memory");
}
#define CP_COMMIT() asm volatile("cp.async.commit_group;" ::: "memory")
#define CP_WAIT1()  asm volatile("cp.async.wait_group 1;" ::: "memory")

// =====================================================================================
// prepack: transpose W[K][N] -> single fp16 [n*rowMul+rowOff][ldo] (k-contiguous)
// =====================================================================================
__global__ void prepack_kernel(const float* __restrict__ W, __half* __restrict__ H,
                               int K, int N, int ldo, int rowMul, int rowOff) {
    __shared__ float t[32][33];
    int tx = threadIdx.x, ty = threadIdx.y;
    int n0 = blockIdx.x * 32, k0 = blockIdx.y * 32;
#pragma unroll
    for (int j = 0; j < 4; j++) {
        int k = k0 + ty + j * 8, n = n0 + tx;
        if (k < K && n < N) t[ty + j * 8][tx] = W[(size_t)k * N + n];
    }
    __syncthreads();
#pragma unroll
    for (int j = 0; j < 4; j++) {
        int n = n0 + ty + j * 8, k = k0 + tx;
        if (k < K && n < N)
            H[(size_t)(n * rowMul + rowOff) * ldo + k] = __float2half(t[tx][ty + j * 8]);
    }
}

// =====================================================================================
// NT tensor-core GEMM, 2-term FP16 (A split hi/lo, B single), cp.async pipeline.
//   C[M,N] = A[M,K] @ B[N,K]^T.
//   gridDim.z > 1: K-split; each z writes its own partial at Cf + z*partStride.
//   geglu_mode: interleaved gate/up epilogue (z must be 1).
// =====================================================================================
#define GSTAGES 3
#define GEMM_SMEM (GSTAGES * 12288)

__global__ __launch_bounds__(256, 2) void gemm_kernel(
    const __half* __restrict__ Ah, const __half* __restrict__ Al,
    const __half* __restrict__ Bh,
    float* __restrict__ Cf, __half* __restrict__ GoH, __half* __restrict__ GoL,
    int lda, int ldb, int ldc, int M, int N, int K, int geglu_mode, size_t partStride) {
    extern __shared__ __align__(16) unsigned short sm[];
    unsigned smBase = smem_u32(sm);
    const int tid = threadIdx.x;
    const int m0 = blockIdx.y * 128, n0 = blockIdx.x * 128;
    const int kLen = K / gridDim.z;
    const int kStart = blockIdx.z * kLen;
    Cf += (size_t)blockIdx.z * partStride;
    const int aRow = tid >> 1, aK = (tid & 1) * 8;
    const int physSt = (aK >> 3) ^ ((aRow >> 2) & 1);
    const unsigned stOff = aRow * 32 + physSt * 16;
    const __half* ApH = Ah + (size_t)(m0 + aRow) * lda + kStart + aK;
    const __half* ApL = Al + (size_t)(m0 + aRow) * lda + kStart + aK;
    const int gn = n0 + aRow;
    const unsigned bBytes = (gn < N) ? 16u : 0u;
    const int gnc = (gn < N) ? gn : (N - 1);
    const __half* BpH = Bh + (size_t)gnc * ldb + kStart + aK;

    const int lane = tid & 31, warp = tid >> 5;
    const int g = lane >> 2, t = lane & 3;
    const int wM = (warp >> 2) * 64, wN = (warp & 3) * 32;
    const int lr = lane & 15, kc = lane >> 4;
    unsigned offA[4], offB[2];
#pragma unroll
    for (int mt = 0; mt < 4; mt++) {
        int r = wM + mt * 16 + lr;
        int ph = kc ^ ((r >> 2) & 1);
        offA[mt] = r * 32 + ph * 16;
    }
#pragma unroll
    for (int p = 0; p < 2; p++) {
        int r = wN + p * 16 + lr;
        int ph = kc ^ ((r >> 2) & 1);
        offB[p] = 8192 + r * 32 + ph * 16;
    }

    float acc[4][4][4];
#pragma unroll
    for (int i = 0; i < 4; i++)
#pragma unroll
        for (int j = 0; j < 4; j++)
#pragma unroll
            for (int r = 0; r < 4; r++) acc[i][j][r] = 0.f;

    const int nT = kLen >> 4;
    auto LOADA = [&](int stage, int k0) {
        unsigned d = smBase + stage * 12288 + stOff;
        cp16(d, ApH + k0, 16u);
        cp16(d + 4096, ApL + k0, 16u);
        cp16(d + 8192, BpH + k0, bBytes);
        CP_COMMIT();
    };

    LOADA(0, 0);
    if (nT > 1) LOADA(1, 16);
    int stage = 0;
    for (int tt = 0; tt < nT; ++tt) {
        CP_WAIT1();
        __syncthreads();
        if (tt + 2 < nT) {
            int ns = stage + 2;
            if (ns >= GSTAGES) ns -= GSTAGES;
            LOADA(ns, (tt + 2) << 4);
        }
        unsigned bo = smBase + stage * 12288;
        unsigned a_h[4][4], a_l[4][4], b_h[2][4];
#pragma unroll
        for (int mt = 0; mt < 4; mt++) {
            ldsm4(bo + offA[mt], a_h[mt][0], a_h[mt][1], a_h[mt][2], a_h[mt][3]);
            ldsm4(bo + offA[mt] + 4096, a_l[mt][0], a_l[mt][1], a_l[mt][2], a_l[mt][3]);
        }
#pragma unroll
        for (int p = 0; p < 2; p++)
            ldsm4(bo + offB[p], b_h[p][0], b_h[p][1], b_h[p][2], b_h[p][3]);
#pragma unroll
        for (int mt = 0; mt < 4; mt++)
#pragma unroll
            for (int nt = 0; nt < 4; nt++) {
                int p = nt >> 1, od = nt & 1;
                unsigned b0 = b_h[p][od], b1 = b_h[p][od + 2];
                mma_f16(acc[mt][nt], a_h[mt], b0, b1);
                mma_f16(acc[mt][nt], a_l[mt], b0, b1);
            }
        if (++stage == GSTAGES) stage = 0;
    }

    if (geglu_mode) {
#pragma unroll
        for (int mt = 0; mt < 4; mt++) {
            int r = m0 + wM + mt * 16 + g;
#pragma unroll
            for (int nt = 0; nt < 4; nt++) {
                int c = n0 + wN + nt * 8 + 2 * t;    // even; (gate, up) pair
                if (c < N) {
                    int j = c >> 1;
                    float gv0 = acc[mt][nt][0], uv0 = acc[mt][nt][1];
                    float gv1 = acc[mt][nt][2], uv1 = acc[mt][nt][3];
                    float t0 = 0.7978845608028654f * (gv0 + 0.044715f * gv0 * gv0 * gv0);
                    float t1 = 0.7978845608028654f * (gv1 + 0.044715f * gv1 * gv1 * gv1);
                    float o0 = 0.5f * gv0 * (1.f + tanhf(t0)) * uv0;
                    float o1 = 0.5f * gv1 * (1.f + tanhf(t1)) * uv1;
                    splitStoreH(o0, GoH, GoL, (size_t)r * FF_PAD + j);
                    splitStoreH(o1, GoH, GoL, (size_t)(r + 8) * FF_PAD + j);
                }
            }
        }
    } else {
#pragma unroll
        for (int mt = 0; mt < 4; mt++) {
            int r = m0 + wM + mt * 16 + g;
#pragma unroll
            for (int nt = 0; nt < 4; nt++) {
                int c = n0 + wN + nt * 8 + 2 * t;
                if (c < N) {
                    *(float2*)(Cf + (size_t)r * ldc + c) =
                        make_float2(acc[mt][nt][0], acc[mt][nt][1]);
                    *(float2*)(Cf + (size_t)(r + 8) * ldc + c) =
                        make_float2(acc[mt][nt][2], acc[mt][nt][3]);
                }
            }
        }
    }
}

// =====================================================================================
// Flash attention (3xBF16) — per (q-tile 128, bn) block, online softmax.
// Epilogue emits fp16 hi/lo att for the Wo GEMM.
// =====================================================================================
#define SK_OFF 0
#define SKL_OFF 11264
#define SV_OFF 22528
#define SVL_OFF 33408
#define FLASH_SMEM ((22528 + 21760) * 2)

__global__ __launch_bounds__(256, 1) void flash_kernel(
    const bf16* __restrict__ qH, const bf16* __restrict__ qL,
    const bf16* __restrict__ kH, const bf16* __restrict__ kL,
    const bf16* __restrict__ vH, const bf16* __restrict__ vL,
    __half* __restrict__ attH, __half* __restrict__ attL) {
    extern __shared__ __align__(16) unsigned short sm[];
    unsigned short* sKh = sm + SK_OFF;
    unsigned short* sKl = sm + SKL_OFF;
    unsigned short* sVh = sm + SV_OFF;
    unsigned short* sVl = sm + SVL_OFF;
    unsigned smBase = smem_u32(sm);

    const int tid = threadIdx.x;
    const int qt = blockIdx.x, bn = blockIdx.y;
    const int b = bn >> 4, n = bn & 15;
    const int lane = tid & 31, warp = tid >> 5;
    const int g = lane >> 2, t = lane & 3;
    const int lr = lane & 15, kh = lane >> 4;
    const int qRow0 = warp * 16;

    const size_t qkStride = (size_t)NHEADS * HPAD;
    const size_t qBase = ((size_t)(b * L + qt * 128) * NHEADS + n) * HPAD;
    const size_t kBase = ((size_t)(b * L) * NHEADS + n) * HPAD;
    const size_t vBase = ((size_t)bn * HPAD) * L;

#pragma unroll
    for (int i = 0; i < 5; i++) {
        int idx = tid + i * 256;
        int r = idx / 10, c8 = (idx % 10) * 8;
        size_t go = qBase + (size_t)r * qkStride + c8;
        *(uint4*)&sKh[r * 88 + c8] = *(const uint4*)(qH + go);
        *(uint4*)&sKl[r * 88 + c8] = *(const uint4*)(qL + go);
    }
    __syncthreads();
    unsigned qh[5][4], ql[5][4];
#pragma unroll
    for (int ch = 0; ch < 5; ch++) {
        unsigned a = smBase + ((qRow0 + lr) * 88 + ch * 16 + kh * 8) * 2;
        ldsm4(a, qh[ch][0], qh[ch][1], qh[ch][2], qh[ch][3]);
        ldsm4(a + SKL_OFF * 2, ql[ch][0], ql[ch][1], ql[ch][2], ql[ch][3]);
    }
    __syncthreads();

    float Oacc[10][4];
#pragma unroll
    for (int i = 0; i < 10; i++)
#pragma unroll
        for (int j = 0; j < 4; j++) Oacc[i][j] = 0.f;
    float mA = -1e30f, mB = -1e30f, lA = 0.f, lB = 0.f;

    for (int st = 0; st < 8; st++) {
#pragma unroll
        for (int i = 0; i < 5; i++) {
            int idx = tid + i * 256;
            int r = idx / 10, c8 = (idx % 10) * 8;
            size_t go = kBase + (size_t)(st * 128 + r) * qkStride + c8;
            *(uint4*)&sKh[r * 88 + c8] = *(const uint4*)(kH + go);
            *(uint4*)&sKl[r * 88 + c8] = *(const uint4*)(kL + go);
            int vr = idx / 16, vc = (idx % 16) * 8;
            size_t gv = vBase + (size_t)vr * L + st * 128 + vc;
            *(uint4*)&sVh[vr * 136 + vc] = *(const uint4*)(vH + gv);
            *(uint4*)&sVl[vr * 136 + vc] = *(const uint4*)(vL + gv);
        }
        __syncthreads();

        float sacc[16][4];
#pragma unroll
        for (int i = 0; i < 16; i++)
#pragma unroll
            for (int j = 0; j < 4; j++) sacc[i][j] = 0.f;
#pragma unroll
        for (int ch = 0; ch < 5; ch++) {
#pragma unroll
            for (int ng = 0; ng < 8; ng++) {
                unsigned a = smBase + ((ng * 16 + lr) * 88 + ch * 16 + kh * 8) * 2;
                unsigned h0, h1, h2, h3, l0, l1, l2, l3;
                ldsm4(a, h0, h1, h2, h3);
                ldsm4(a + SKL_OFF * 2, l0, l1, l2, l3);
                mma3b(sacc[2 * ng], qh[ch], ql[ch], h0, h2, l0, l2);
                mma3b(sacc[2 * ng + 1], qh[ch], ql[ch], h1, h3, l1, l3);
            }
        }

        float tmA = -1e30f, tmB = -1e30f;
#pragma unroll
        for (int i = 0; i < 16; i++) {
            tmA = fmaxf(tmA, fmaxf(sacc[i][0], sacc[i][1]));
            tmB = fmaxf(tmB, fmaxf(sacc[i][2], sacc[i][3]));
        }
        tmA = fmaxf(tmA, __shfl_xor_sync(0xffffffffu, tmA, 1));
        tmA = fmaxf(tmA, __shfl_xor_sync(0xffffffffu, tmA, 2));
        tmB = fmaxf(tmB, __shfl_xor_sync(0xffffffffu, tmB, 1));
        tmB = fmaxf(tmB, __shfl_xor_sync(0xffffffffu, tmB, 2));
        float mnA = fmaxf(mA, tmA), mnB = fmaxf(mB, tmB);
        float fA = __expf(mA - mnA), fB = __expf(mB - mnB);
        mA = mnA; mB = mnB;
        float sA = 0.f, sB = 0.f;
#pragma unroll
        for (int i = 0; i < 16; i++) {
            sacc[i][0] = __expf(sacc[i][0] - mnA);
            sacc[i][1] = __expf(sacc[i][1] - mnA);
            sacc[i][2] = __expf(sacc[i][2] - mnB);
            sacc[i][3] = __expf(sacc[i][3] - mnB);
            sA += sacc[i][0] + sacc[i][1];
            sB += sacc[i][2] + sacc[i][3];
        }
        sA += __shfl_xor_sync(0xffffffffu, sA, 1);
        sA += __shfl_xor_sync(0xffffffffu, sA, 2);
        sB += __shfl_xor_sync(0xffffffffu, sB, 1);
        sB += __shfl_xor_sync(0xffffffffu, sB, 2);
        lA = lA * fA + sA;
        lB = lB * fB + sB;
#pragma unroll
        for (int i = 0; i < 10; i++) {
            Oacc[i][0] *= fA; Oacc[i][1] *= fA;
            Oacc[i][2] *= fB; Oacc[i][3] *= fB;
        }

#pragma unroll
        for (int kc = 0; kc < 8; kc++) {
            unsigned ah[4], al[4];
            pack2b(sacc[2 * kc][0], sacc[2 * kc][1], ah[0], al[0]);
            pack2b(sacc[2 * kc][2], sacc[2 * kc][3], ah[1], al[1]);
            pack2b(sacc[2 * kc + 1][0], sacc[2 * kc + 1][1], ah[2], al[2]);
            pack2b(sacc[2 * kc + 1][2], sacc[2 * kc + 1][3], ah[3], al[3]);
#pragma unroll
            for (int vg = 0; vg < 5; vg++) {
                unsigned a = smBase + SV_OFF * 2 + ((vg * 16 + lr) * 136 + kc * 16 + kh * 8) * 2;
                unsigned h0, h1, h2, h3, l0, l1, l2, l3;
                ldsm4(a, h0, h1, h2, h3);
                ldsm4(a + (SVL_OFF - SV_OFF) * 2, l0, l1, l2, l3);
                mma3b(Oacc[2 * vg], ah, al, h0, h2, l0, l2);
                mma3b(Oacc[2 * vg + 1], ah, al, h1, h3, l1, l3);
            }
        }
        __syncthreads();
    }

    float invA = 1.f / lA, invB = 1.f / lB;
    int row0 = b * L + qt * 128 + qRow0 + g;
#pragma unroll
    for (int nt = 0; nt < 9; nt++) {
        int c = n * HDIM + nt * 8 + 2 * t;
        size_t i0 = (size_t)row0 * DIM + c;
        size_t i1 = (size_t)(row0 + 8) * DIM + c;
        splitStoreH(Oacc[nt][0] * invA, attH, attL, i0);
        splitStoreH(Oacc[nt][1] * invA, attH, attL, i0 + 1);
        splitStoreH(Oacc[nt][2] * invB, attH, attL, i1);
        splitStoreH(Oacc[nt][3] * invB, attH, attL, i1 + 1);
    }
}

// ---------------- patchify -> fp16 hi/lo ----------------
__global__ void patchify_kernel(const float* __restrict__ img, __half* __restrict__ PH,
                                __half* __restrict__ PL) {
    int idx = blockIdx.x * blockDim.x + threadIdx.x;
    if (idx >= BL * PATCHD) return;
    int bl = idx / PATCHD, j = idx % PATCHD;
    int b = bl >> 10, l = bl & 1023;
    int gy = l >> 5, gx = l & 31;
    int py = j / 48, r = j % 48;
    int px = r / 3, c = r % 3;
    int row = gy * 16 + py, col = gx * 16 + px;
    float v = 2.0f * img[(((size_t)b * 512 + row) * 512 + col) * 3 + c] - 1.0f;
    splitStoreH(v, PH, PL, idx);
}

// ---------------- fused entry: x = op0+op1+posemb; h = rms(x)*(1+nsc) -> fp16 hi/lo -----
__global__ void posemb_rms_kernel(const float* __restrict__ op, const float* __restrict__ pe,
                                  const float* __restrict__ nsc, float* __restrict__ x,
                                  __half* __restrict__ outH, __half* __restrict__ outL) {
    int row = blockIdx.x;
    int l = row & 1023;
    int posx = l & 31, posy = l >> 5;
    const float* pe0 = pe + (size_t)(posx * 2 + 0) * DIM;
    const float* pe1 = pe + (size_t)(posy * 2 + 1) * DIM;
    const float* p0 = op + (size_t)row * DIM;
    const float* p1 = op + (size_t)(BL + row) * DIM;
    float xv[5];
    float s = 0.f;
#pragma unroll
    for (int j = 0; j < 5; j++) {
        int i = threadIdx.x + j * 256;
        if (i < DIM) {
            xv[j] = p0[i] + p1[i] + pe0[i] + pe1[i];
            s += xv[j] * xv[j];
            x[(size_t)row * DIM + i] = xv[j];
        } else xv[j] = 0.f;
    }
    __shared__ float red[256];
    red[threadIdx.x] = s; __syncthreads();
    for (int st = 128; st > 0; st >>= 1) {
        if (threadIdx.x < st) red[threadIdx.x] += red[threadIdx.x + st];
        __syncthreads();
    }
    float rs = rsqrtf(red[0] / (float)DIM + EPS);
#pragma unroll
    for (int j = 0; j < 5; j++) {
        int i = threadIdx.x + j * 256;
        if (i < DIM)
            splitStoreH(xv[j] * rs * (1.f + nsc[i]), outH, outL, (size_t)row * DIM + i);
    }
}

// ---------------- fused: x += rms(op0+op1)*(1+rsc); h = rms(x)*(1+nsc) -> fp16 hi/lo ----
__global__ void resid_rms_norm_kernel(float* __restrict__ x, const float* __restrict__ op,
                                      const float* __restrict__ rsc,
                                      const float* __restrict__ nsc,
                                      __half* __restrict__ outH, __half* __restrict__ outL) {
    int row = blockIdx.x;
    const float* p0 = op + (size_t)row * DIM;
    const float* p1 = op + (size_t)(BL + row) * DIM;
    float* px = x + (size_t)row * DIM;
    float ov[5], xv[5];
    float s = 0.f;
#pragma unroll
    for (int j = 0; j < 5; j++) {
        int i = threadIdx.x + j * 256;
        if (i < DIM) { ov[j] = p0[i] + p1[i]; xv[j] = px[i]; s += ov[j] * ov[j]; }
        else { ov[j] = 0.f; xv[j] = 0.f; }
    }
    __shared__ float red[256];
    red[threadIdx.x] = s; __syncthreads();
    for (int st = 128; st > 0; st >>= 1) {
        if (threadIdx.x < st) red[threadIdx.x] += red[threadIdx.x + st];
        __syncthreads();
    }
    float rs = rsqrtf(red[0] / (float)DIM + EPS);
    __syncthreads();
    float s2 = 0.f;
#pragma unroll
    for (int j = 0; j < 5; j++) {
        int i = threadIdx.x + j * 256;
        if (i < DIM) {
            xv[j] += ov[j] * rs * (1.f + rsc[i]);
            s2 += xv[j] * xv[j];
            px[i] = xv[j];
        }
    }
    red[threadIdx.x] = s2; __syncthreads();
    for (int st = 128; st > 0; st >>= 1) {
        if (threadIdx.x < st) red[threadIdx.x] += red[threadIdx.x + st];
        __syncthreads();
    }
    float rs2 = rsqrtf(red[0] / (float)DIM + EPS);
#pragma unroll
    for (int j = 0; j < 5; j++) {
        int i = threadIdx.x + j * 256;
        if (i < DIM)
            splitStoreH(xv[j] * rs2 * (1.f + nsc[i]), outH, outL, (size_t)row * DIM + i);
    }
}

// ---------------- fused: x += rms(op0+op1)*(1+rsc); out = (x*sqrtD - bias)*scale ---------
__global__ void resid_final_kernel(const float* __restrict__ x, const float* __restrict__ op,
                                   const float* __restrict__ rsc,
                                   const float* __restrict__ bias,
                                   const float* __restrict__ scl, float* __restrict__ out) {
    int row = blockIdx.x;
    const float* p0 = op + (size_t)row * DIM;
    const float* p1 = op + (size_t)(BL + row) * DIM;
    const float* px = x + (size_t)row * DIM;
    float ov[5];
    float s = 0.f;
#pragma unroll
    for (int j = 0; j < 5; j++) {
        int i = threadIdx.x + j * 256;
        ov[j] = (i < DIM) ? (p0[i] + p1[i]) : 0.f;
        s += ov[j] * ov[j];
    }
    __shared__ float red[256];
    red[threadIdx.x] = s; __syncthreads();
    for (int st = 128; st > 0; st >>= 1) {
        if (threadIdx.x < st) red[threadIdx.x] += red[threadIdx.x + st];
        __syncthreads();
    }
    float rs = rsqrtf(red[0] / (float)DIM + EPS);
#pragma unroll
    for (int j = 0; j < 5; j++) {
        int i = threadIdx.x + j * 256;
        if (i < DIM) {
            float xn = px[i] + ov[j] * rs * (1.f + rsc[i]);
            out[(size_t)row * DIM + i] = (xn * 33.941125496954285f - bias[i]) * scl[i];
        }
    }
}

// ---------------- fused per-head RMS (+2D RoPE): blockIdx.y = 0:q 1:k 2:v (bf16 out) -----
// Sums the two K-split partials of qkv.
__global__ void head_finish_fused(const float* __restrict__ qkvp,
                                  const float* __restrict__ qn, const float* __restrict__ kn,
                                  const float* __restrict__ vn,
                                  bf16* __restrict__ qpH, bf16* __restrict__ qpL,
                                  bf16* __restrict__ kpH, bf16* __restrict__ kpL,
                                  bf16* __restrict__ vtH, bf16* __restrict__ vtL,
                                  float qk_scale) {
    int sec = blockIdx.y;
    const float* scale = (sec == 0) ? qn : ((sec == 1) ? kn : vn);
    float premul = (sec == 0) ? qk_scale : 1.f;
    int warp = threadIdx.x >> 5, lane = threadIdx.x & 31;
    int item = blockIdx.x * 8 + warp;
    int token = item >> 4;
    int head = item & 15;
    const float* p = qkvp + (size_t)token * QKVD + sec * DIM + head * HDIM;
    const float* p2 = p + (size_t)BL * QKVD;
    float v0 = p[lane] + p2[lane];
    float v1 = p[lane + 32] + p2[lane + 32];
    float v2 = (lane < 8) ? (p[lane + 64] + p2[lane + 64]) : 0.f;
    float s = v0 * v0 + v1 * v1 + v2 * v2;
#pragma unroll
    for (int off = 16; off; off >>= 1) s += __shfl_xor_sync(0xffffffffu, s, off);
    float rs = rsqrtf(s / (float)HDIM + EPS) * premul;
    __shared__ float buf[8][HDIM];
    buf[warp][lane] = v0 * rs * (1.f + scale[lane]);
    buf[warp][lane + 32] = v1 * rs * (1.f + scale[lane + 32]);
    if (lane < 8) buf[warp][lane + 64] = v2 * rs * (1.f + scale[lane + 64]);
    __syncwarp();
    if (sec < 2) {
        int l = token & 1023;
        float posx = (float)(l & 31), posy = (float)(l >> 5);
        for (int pp = lane; pp < 36; pp += 32) {
            int j = (pp < 18) ? pp : (pp - 18);
            float pos = (pp < 18) ? posx : posy;
            int d1 = (pp < 18) ? pp : (pp + 18);
            int d2 = d1 + 18;
            float ts = powf(100.f, (float)j / 18.f);
            float ang = pos / ts;
            float sn, cs;
            sincosf(ang, &sn, &cs);
            float a = buf[warp][d1], b2 = buf[warp][d2];
            buf[warp][d1] = a * cs - b2 * sn;
            buf[warp][d2] = b2 * cs + a * sn;
        }
        __syncwarp();
    }
    if (sec < 2) {
        bf16* oH = (sec == 0) ? qpH : kpH;
        bf16* oL = (sec == 0) ? qpL : kpL;
        size_t base = ((size_t)token * NHEADS + head) * HPAD;
        splitStoreB(buf[warp][lane], oH, oL, base + lane);
        splitStoreB(buf[warp][lane + 32], oH, oL, base + lane + 32);
        if (lane < 8) splitStoreB(buf[warp][lane + 64], oH, oL, base + lane + 64);
    } else {
        int b = token >> 10, l = token & 1023;
        size_t base = ((size_t)(b * NHEADS + head) * HPAD) * L + l;
        splitStoreB(buf[warp][lane], vtH, vtL, base + (size_t)lane * L);
        splitStoreB(buf[warp][lane + 32], vtH, vtL, base + (size_t)(lane + 32) * L);
        if (lane < 8) splitStoreB(buf[warp][lane + 64], vtH, vtL, base + (size_t)(lane + 64) * L);
    }
}

// ---------------- launcher ----------------
extern "C" void kernel_launch(void* const* d_in, const int* in_sizes, int n_in,
                              void* d_out, int out_size) {
    const float* inputs    = (const float*)d_in[0];
    const float* Wp        = (const float*)d_in[1];
    const float* posemb    = (const float*)d_in[2];
    const float* Wq        = (const float*)d_in[3];
    const float* Wk        = (const float*)d_in[4];
    const float* Wv        = (const float*)d_in[5];
    const float* Wo        = (const float*)d_in[6];
    const float* Wg        = (const float*)d_in[7];
    const float* Wu        = (const float*)d_in[8];
    const float* Wd        = (const float*)d_in[9];
    const float* qn        = (const float*)d_in[10];
    const float* kn        = (const float*)d_in[11];
    const float* vn        = (const float*)d_in[12];
    const float* pre_attn  = (const float*)d_in[13];
    const float* post_attn = (const float*)d_in[14];
    const float* pre_ffw   = (const float*)d_in[15];
    const float* post_ffw  = (const float*)d_in[16];
    const float* std_bias  = (const float*)d_in[17];
    const float* std_scale = (const float*)d_in[18];
    float* out = (float*)d_out;

    float *x, *op, *qkvp;
    cudaGetSymbolAddress((void**)&x, g_x);
    cudaGetSymbolAddress((void**)&op, g_op);
    cudaGetSymbolAddress((void**)&qkvp, g_qkvp);
    __half *patH, *patL, *hH, *hL, *attH, *attL, *gH, *gL;
    cudaGetSymbolAddress((void**)&patH, g_patH); cudaGetSymbolAddress((void**)&patL, g_patL);
    cudaGetSymbolAddress((void**)&hH, g_hH);     cudaGetSymbolAddress((void**)&hL, g_hL);
    cudaGetSymbolAddress((void**)&attH, g_attH); cudaGetSymbolAddress((void**)&attL, g_attL);
    cudaGetSymbolAddress((void**)&gH, g_gH);     cudaGetSymbolAddress((void**)&gL, g_gL);
    bf16 *qpH, *qpL, *kpH, *kpL, *vtH, *vtL;
    cudaGetSymbolAddress((void**)&qpH, g_qpH);   cudaGetSymbolAddress((void**)&qpL, g_qpL);
    cudaGetSymbolAddress((void**)&kpH, g_kpH);   cudaGetSymbolAddress((void**)&kpL, g_kpL);
    cudaGetSymbolAddress((void**)&vtH, g_vtH);   cudaGetSymbolAddress((void**)&vtL, g_vtL);
    __half *WpH, *WqkvH, *WoH, *WguH, *WdH;
    cudaGetSymbolAddress((void**)&WpH, g_WpH);
    cudaGetSymbolAddress((void**)&WqkvH, g_WqkvH);
    cudaGetSymbolAddress((void**)&WoH, g_WoH);
    cudaGetSymbolAddress((void**)&WguH, g_WguH);
    cudaGetSymbolAddress((void**)&WdH, g_WdH);

    const float qk_scale = 0.11785113019775793f;  // 1/sqrt(72)
    dim3 tb(32, 8);
    const size_t PS_D = (size_t)BL * DIM;      // partial stride for DIM outputs
    const size_t PS_Q = (size_t)BL * QKVD;     // partial stride for QKV outputs

    static cudaStream_t s2 = nullptr;
    static cudaEvent_t evFork, evWp, evL[NLAYERS];
    static bool attr_set = false;
    if (!attr_set) {
        cudaFuncSetAttribute(flash_kernel, cudaFuncAttributeMaxDynamicSharedMemorySize,
                             FLASH_SMEM);
        cudaFuncSetAttribute(gemm_kernel, cudaFuncAttributeMaxDynamicSharedMemorySize,
                             GEMM_SMEM);
        int loPri, hiPri;
        cudaDeviceGetStreamPriorityRange(&loPri, &hiPri);
        cudaStreamCreateWithPriority(&s2, cudaStreamNonBlocking, loPri);
        cudaEventCreateWithFlags(&evFork, cudaEventDisableTiming);
        cudaEventCreateWithFlags(&evWp, cudaEventDisableTiming);
        for (int i = 0; i < NLAYERS; i++)
            cudaEventCreateWithFlags(&evL[i], cudaEventDisableTiming);
        attr_set = true;
    }

    // ---- fork prepack stream (single fp16 weights, low priority) ----
    cudaEventRecord(evFork, 0);
    cudaStreamWaitEvent(s2, evFork, 0);
    prepack_kernel<<<dim3((DIM + 31) / 32, (PATCHD + 31) / 32), tb, 0, s2>>>(
        Wp, WpH, PATCHD, DIM, PATCHD, 1, 0);
    cudaEventRecord(evWp, s2);
    for (int i = 0; i < NLAYERS; i++) {
        size_t so = (size_t)i * DIM * DIM;
        size_t qo = (size_t)i * QKVD * DIM;
        prepack_kernel<<<dim3(36, 36), tb, 0, s2>>>(Wq + so, WqkvH + qo, DIM, DIM, DIM, 1, 0);
        prepack_kernel<<<dim3(36, 36), tb, 0, s2>>>(Wk + so, WqkvH + qo + (size_t)DIM * DIM,
                                                    DIM, DIM, DIM, 1, 0);
        prepack_kernel<<<dim3(36, 36), tb, 0, s2>>>(Wv + so, WqkvH + qo + 2 * (size_t)DIM * DIM,
                                                    DIM, DIM, DIM, 1, 0);
        prepack_kernel<<<dim3(36, 36), tb, 0, s2>>>(Wo + so, WoH + so, DIM, DIM, DIM, 1, 0);
        size_t fo = (size_t)i * DIM * FF;
        size_t go = (size_t)i * GUD * DIM;
        size_t fp = (size_t)i * DIM * FF_PAD;
        prepack_kernel<<<dim3((FF + 31) / 32, 36), tb, 0, s2>>>(Wg + fo, WguH + go,
                                                                DIM, FF, DIM, 2, 0);
        prepack_kernel<<<dim3((FF + 31) / 32, 36), tb, 0, s2>>>(Wu + fo, WguH + go,
                                                                DIM, FF, DIM, 2, 1);
        prepack_kernel<<<dim3(36, (FF + 31) / 32), tb, 0, s2>>>(Wd + fo, WdH + fp,
                                                                FF, DIM, FF_PAD, 1, 0);
        cudaEventRecord(evL[i], s2);
    }

    // ---- entry ----
    patchify_kernel<<<(BL * PATCHD + 255) / 256, 256>>>(inputs, patH, patL);
    cudaStreamWaitEvent(0, evWp, 0);
    gemm_kernel<<<dim3(9, 16, 2), 256, GEMM_SMEM>>>(patH, patL, WpH, op, nullptr, nullptr,
                                                    PATCHD, PATCHD, DIM, BL, DIM, PATCHD,
                                                    0, PS_D);
    posemb_rms_kernel<<<BL, 256>>>(op, posemb, pre_attn, x, hH, hL);

    for (int i = 0; i < NLAYERS; i++) {
        size_t so = (size_t)i * DIM * DIM;
        size_t qo = (size_t)i * QKVD * DIM;
        size_t go = (size_t)i * GUD * DIM;
        size_t fp = (size_t)i * DIM * FF_PAD;

        cudaStreamWaitEvent(0, evL[i], 0);

        // attention
        gemm_kernel<<<dim3(27, 16, 2), 256, GEMM_SMEM>>>(hH, hL, WqkvH + qo, qkvp, nullptr,
                                                         nullptr, DIM, DIM, QKVD,
                                                         BL, QKVD, DIM, 0, PS_Q);
        head_finish_fused<<<dim3(BL * NHEADS / 8, 3), 256>>>(qkvp, qn + i * HDIM,
                                                             kn + i * HDIM, vn + i * HDIM,
                                                             qpH, qpL, kpH, kpL,
                                                             vtH, vtL, qk_scale);
        flash_kernel<<<dim3(8, 32), 256, FLASH_SMEM>>>(qpH, qpL, kpH, kpL, vtH, vtL,
                                                       attH, attL);
        gemm_kernel<<<dim3(9, 16, 2), 256, GEMM_SMEM>>>(attH, attL, WoH + so, op, nullptr,
                                                        nullptr, DIM, DIM, DIM,
                                                        BL, DIM, DIM, 0, PS_D);
        resid_rms_norm_kernel<<<BL, 256>>>(x, op, post_attn + i * DIM, pre_ffw + i * DIM,
                                           hH, hL);

        // GeGLU MLP: gate/up GEMM with fused geglu epilogue -> gH/gL
        gemm_kernel<<<dim3(68, 16, 1), 256, GEMM_SMEM>>>(hH, hL, WguH + go, nullptr, gH, gL,
                                                         DIM, DIM, 0, BL, GUD, DIM, 1, 0);
        gemm_kernel<<<dim3(9, 16, 2), 256, GEMM_SMEM>>>(gH, gL, WdH + fp, op, nullptr,
                                                        nullptr, FF_PAD, FF_PAD, DIM,
                                                        BL, DIM, FF_PAD, 0, PS_D);
        if (i < NLAYERS - 1) {
            resid_rms_norm_kernel<<<BL, 256>>>(x, op, post_ffw + i * DIM,
                                               pre_attn + (i + 1) * DIM, hH, hL);
        } else {
            resid_final_kernel<<<BL, 256>>>(x, op, post_ffw + i * DIM, std_bias, std_scale,
                                            out);
        }
    }
}